// round 12
// baseline (speedup 1.0000x reference)
#include <cuda_runtime.h>
#include <cuda_bf16.h>
#include <math.h>
#include <stdint.h>

#define BATCH 65536

// ---------------- scratch ----------------
__device__ float g_res[(size_t)BATCH * 64];
__device__ float g_hh[(size_t)BATCH * 1536];
__device__ float g_chh[(size_t)BATCH * 256];
__device__ double g_loss;

// tf32 hi/lo interleaved activation buffers (float2 per element: x=hi, y=lo)
__device__ float2 g_f2[(size_t)BATCH * 832];
__device__ float2 g_z12[(size_t)BATCH * 512];
__device__ float2 g_z22[(size_t)BATCH * 256];
__device__ float2 g_z32[(size_t)BATCH * 128];
__device__ float2 g_ew2[598016];

// bf16 pair interleaved buffers (uint2 per k-pair: x=hi bf16x2, y=lo bf16x2)
__device__ uint2 g_zq2[(size_t)BATCH * 32];
__device__ uint2 g_s12[(size_t)BATCH * 64];
__device__ uint2 g_s22[(size_t)BATCH * 128];
__device__ uint2 g_s32[(size_t)BATCH * 256];
__device__ uint2 g_hl2[(size_t)BATCH * 768];
__device__ uint2 g_ch2[(size_t)BATCH * 128];
__device__ uint2 g_w2[1142784];

__global__ void zero_loss_kernel() { g_loss = 0.0; }

__global__ void finalize_kernel(float* out_loss) {
    float v = (float)(g_loss / ((double)BATCH * 64.0));
    out_loss[0] = v;
    out_loss[1] = v;
}

// ---------------- helpers ----------------
__device__ __forceinline__ float tf32_round(float x) {
    uint32_t r;
    asm("cvt.rna.tf32.f32 %0, %1;" : "=r"(r) : "f"(x));
    return __uint_as_float(r);
}

__device__ __forceinline__ void mma_tf32(float* d, const uint32_t* a, const uint32_t* b) {
    asm volatile(
        "mma.sync.aligned.m16n8k8.row.col.f32.tf32.tf32.f32 "
        "{%0,%1,%2,%3}, {%4,%5,%6,%7}, {%8,%9}, {%0,%1,%2,%3};"
        : "+f"(d[0]), "+f"(d[1]), "+f"(d[2]), "+f"(d[3])
        : "r"(a[0]), "r"(a[1]), "r"(a[2]), "r"(a[3]), "r"(b[0]), "r"(b[1]));
}

__device__ __forceinline__ void mma_bf16(float* d, const uint32_t* a, const uint32_t* b) {
    asm volatile(
        "mma.sync.aligned.m16n8k16.row.col.f32.bf16.bf16.f32 "
        "{%0,%1,%2,%3}, {%4,%5,%6,%7}, {%8,%9}, {%0,%1,%2,%3};"
        : "+f"(d[0]), "+f"(d[1]), "+f"(d[2]), "+f"(d[3])
        : "r"(a[0]), "r"(a[1]), "r"(a[2]), "r"(a[3]), "r"(b[0]), "r"(b[1]));
}

__device__ __forceinline__ void split_pack(float x0, float x1, uint32_t& hi, uint32_t& lo) {
    __nv_bfloat16 h0 = __float2bfloat16_rn(x0);
    __nv_bfloat16 h1 = __float2bfloat16_rn(x1);
    __nv_bfloat16 l0 = __float2bfloat16_rn(x0 - __bfloat162float(h0));
    __nv_bfloat16 l1 = __float2bfloat16_rn(x1 - __bfloat162float(h1));
    hi = ((uint32_t)__bfloat16_as_ushort(h1) << 16) | (uint32_t)__bfloat16_as_ushort(h0);
    lo = ((uint32_t)__bfloat16_as_ushort(l1) << 16) | (uint32_t)__bfloat16_as_ushort(l0);
}

__device__ __forceinline__ void cp_async16(uint32_t dst, const void* src) {
    asm volatile("cp.async.cg.shared.global [%0], [%1], 16;" :: "r"(dst), "l"(src));
}

__device__ __forceinline__ uint32_t smem_u32(const void* p) {
    uint32_t a;
    asm("{ .reg .u64 t; cvta.to.shared.u64 t, %1; cvt.u32.u64 %0, t; }" : "=r"(a) : "l"(p));
    return a;
}

// ---------------- pack kernels ----------------
__global__ void pack_enc_tf32(const float* __restrict__ w1, const float* __restrict__ w2,
                              const float* __restrict__ w3, const float* __restrict__ w4,
                              float2* __restrict__ wp)
{
    for (int i = blockIdx.x * blockDim.x + threadIdx.x; i < 598016; i += gridDim.x * blockDim.x) {
        float x;
        if      (i < 425984) x = w1[i];
        else if (i < 557056) x = w2[i - 425984];
        else if (i < 589824) x = w3[i - 557056];
        else                 x = w4[i - 589824];
        float h = tf32_round(x);
        wp[i] = make_float2(h, x - h);
    }
}

__global__ void pack_dec_bf16(const float* __restrict__ d1, const float* __restrict__ d2,
                              const float* __restrict__ d3, const float* __restrict__ s1,
                              const float* __restrict__ s2, const float* __restrict__ c1,
                              const float* __restrict__ c2,
                              uint2* __restrict__ wp)
{
    for (int i = blockIdx.x * blockDim.x + threadIdx.x; i < 1142784; i += gridDim.x * blockDim.x) {
        const float* W; int li, N;
        if      (i < 4096)    { W = d1; li = i;           N = 128;  }
        else if (i < 20480)   { W = d2; li = i - 4096;    N = 256;  }
        else if (i < 86016)   { W = d3; li = i - 20480;   N = 512;  }
        else if (i < 479232)  { W = s1; li = i - 86016;   N = 1536; }
        else if (i < 1069056) { W = s2; li = i - 479232;  N = 768;  }
        else if (i < 1134592) { W = c1; li = i - 1069056; N = 256;  }
        else                  { W = c2; li = i - 1134592; N = 64;   }
        int k2 = li / N, n = li - k2 * N;
        float x0 = W[(size_t)(2 * k2) * N + n];
        float x1 = W[(size_t)(2 * k2 + 1) * N + n];
        uint32_t h, l;
        split_pack(x0, x1, h, l);
        wp[i] = make_uint2(h, l);
    }
}

// ---------------- tf32-3x GEMM: interleaved (hi,lo) float2 operands ----------------
template<int BN, int ACT, int OUT>
__global__ __launch_bounds__(256, 2) void gemm_tf32_pre(
    const float2* __restrict__ A2, const float2* __restrict__ B2,
    float* __restrict__ Cf, float2* __restrict__ C2,
    int M, int N, int K)
{
    constexpr int ASTR = 20;             // float2 units: 16 + 4 pad
    constexpr int A_SZ = 128 * ASTR;     // 2560 float2
    constexpr int BSTR = BN + 4;         // float2 units
    constexpr int B_SZ = 16 * BSTR;
    constexpr int STAGE = A_SZ + B_SZ;   // float2 units
    constexpr int MT = 4;
    constexpr int NT = BN / 32;

    extern __shared__ float2 smem2[];
    const uint32_t sbase = smem_u32(smem2);

    const int tid  = threadIdx.x;
    const int warp = tid >> 5;
    const int lane = tid & 31;
    const int gid  = lane >> 2;
    const int tg   = lane & 3;
    const int mW   = (warp & 1) * 64;
    const int nW   = (warp >> 1) * (BN / 4);

    const size_t bm = (size_t)blockIdx.y * 128;
    const size_t bn = (size_t)blockIdx.x * BN;

    float acc[MT][NT][4];
    #pragma unroll
    for (int i = 0; i < MT; i++)
        #pragma unroll
        for (int j = 0; j < NT; j++)
            #pragma unroll
            for (int r = 0; r < 4; r++) acc[i][j][r] = 0.f;

    auto load_stage = [&](int st, int k0) {
        const uint32_t so = (uint32_t)(st * STAGE);
        // A: 128 rows x 16 float2 = 1024 chunks of 16B (2 float2 each)
        #pragma unroll
        for (int i = 0; i < 4; i++) {
            int c   = tid + i * 256;
            int row = c >> 3;
            int off = (c & 7) << 1;
            cp_async16(sbase + (so + row * ASTR + off) * 8,
                       A2 + (bm + row) * (size_t)K + k0 + off);
        }
        // B: 16 rows x BN float2 = 8*BN chunks
        #pragma unroll
        for (int i = 0; i < BN / 32; i++) {
            int c  = tid + i * 256;
            int r  = c / (BN / 2);
            int cc = (c % (BN / 2)) << 1;
            cp_async16(sbase + (so + A_SZ + r * BSTR + cc) * 8,
                       B2 + (size_t)(k0 + r) * N + bn + cc);
        }
        asm volatile("cp.async.commit_group;" ::: "memory");
    };

    load_stage(0, 0);
    int stage = 0;

    for (int k0 = 0; k0 < K; k0 += 16) {
        const bool more = (k0 + 16) < K;
        if (more) load_stage(stage ^ 1, k0 + 16);
        if (more) asm volatile("cp.async.wait_group 1;" ::: "memory");
        else      asm volatile("cp.async.wait_group 0;" ::: "memory");
        __syncthreads();

        const float2* As = smem2 + stage * STAGE;
        const float2* Bs = As + A_SZ;

        #pragma unroll
        for (int kk = 0; kk < 16; kk += 8) {
            uint32_t ah[MT][4], al[MT][4], bh[NT][2], bl[NT][2];
            #pragma unroll
            for (int mt = 0; mt < MT; mt++) {
                int m0 = mW + mt * 16 + gid;
                float2 a0 = As[m0 * ASTR + kk + tg];
                float2 a1 = As[(m0 + 8) * ASTR + kk + tg];
                float2 a2 = As[m0 * ASTR + kk + tg + 4];
                float2 a3 = As[(m0 + 8) * ASTR + kk + tg + 4];
                ah[mt][0] = __float_as_uint(a0.x); al[mt][0] = __float_as_uint(a0.y);
                ah[mt][1] = __float_as_uint(a1.x); al[mt][1] = __float_as_uint(a1.y);
                ah[mt][2] = __float_as_uint(a2.x); al[mt][2] = __float_as_uint(a2.y);
                ah[mt][3] = __float_as_uint(a3.x); al[mt][3] = __float_as_uint(a3.y);
            }
            #pragma unroll
            for (int nt = 0; nt < NT; nt++) {
                int n0 = nW + nt * 8 + gid;
                float2 b0 = Bs[(kk + tg) * BSTR + n0];
                float2 b1 = Bs[(kk + tg + 4) * BSTR + n0];
                bh[nt][0] = __float_as_uint(b0.x); bl[nt][0] = __float_as_uint(b0.y);
                bh[nt][1] = __float_as_uint(b1.x); bl[nt][1] = __float_as_uint(b1.y);
            }
            #pragma unroll
            for (int mt = 0; mt < MT; mt++)
                #pragma unroll
                for (int nt = 0; nt < NT; nt++) {
                    mma_tf32(acc[mt][nt], al[mt], bh[nt]);
                    mma_tf32(acc[mt][nt], ah[mt], bl[nt]);
                    mma_tf32(acc[mt][nt], ah[mt], bh[nt]);
                }
        }
        __syncthreads();
        stage ^= 1;
    }

    #pragma unroll
    for (int mt = 0; mt < MT; mt++) {
        size_t row0 = bm + mW + mt * 16 + gid;
        size_t row1 = row0 + 8;
        #pragma unroll
        for (int nt = 0; nt < NT; nt++) {
            int col = (int)bn + nW + nt * 8 + 2 * tg;
            float v00 = acc[mt][nt][0], v01 = acc[mt][nt][1];
            float v10 = acc[mt][nt][2], v11 = acc[mt][nt][3];
            if (ACT == 1) {
                v00 = v00 / (1.f + expf(-v00));
                v01 = v01 / (1.f + expf(-v01));
                v10 = v10 / (1.f + expf(-v10));
                v11 = v11 / (1.f + expf(-v11));
            }
            if (OUT == 0) {
                *(float2*)(Cf + row0 * N + col) = make_float2(v00, v01);
                *(float2*)(Cf + row1 * N + col) = make_float2(v10, v11);
            } else {
                float h00 = tf32_round(v00), h01 = tf32_round(v01);
                float h10 = tf32_round(v10), h11 = tf32_round(v11);
                C2[row0 * N + col]     = make_float2(h00, v00 - h00);
                C2[row0 * N + col + 1] = make_float2(h01, v01 - h01);
                C2[row1 * N + col]     = make_float2(h10, v10 - h10);
                C2[row1 * N + col + 1] = make_float2(h11, v11 - h11);
            }
        }
    }
}

// ---------------- bf16x3 GEMM: interleaved (hi,lo) uint2 operands ----------------
template<int BN, int ACT, bool BIAS, int OUT>
__global__ __launch_bounds__(256, 2) void gemm_bf16x3(
    const uint2* __restrict__ A2, const uint2* __restrict__ B2,
    const float* __restrict__ bias,
    float* __restrict__ Cf, uint2* __restrict__ C2,
    int M, int N, int K)
{
    constexpr int ASTR = 20;             // uint2 units: 16 + 4 pad
    constexpr int A_SZ = 128 * ASTR;
    constexpr int BSTR = BN + 4;
    constexpr int B_SZ = 16 * BSTR;
    constexpr int STAGE = A_SZ + B_SZ;
    constexpr int MT = 4;
    constexpr int NT = BN / 32;

    extern __shared__ uint2 usmem2[];
    const uint32_t sbase = smem_u32(usmem2);

    const int tid  = threadIdx.x;
    const int warp = tid >> 5;
    const int lane = tid & 31;
    const int gid  = lane >> 2;
    const int tg   = lane & 3;
    const int mW   = (warp & 1) * 64;
    const int nW   = (warp >> 1) * (BN / 4);

    const size_t bm = (size_t)blockIdx.y * 128;
    const size_t bn = (size_t)blockIdx.x * BN;
    const int K2 = K >> 1;

    float acc[MT][NT][4];
    #pragma unroll
    for (int i = 0; i < MT; i++)
        #pragma unroll
        for (int j = 0; j < NT; j++)
            #pragma unroll
            for (int r = 0; r < 4; r++) acc[i][j][r] = 0.f;

    auto load_stage = [&](int st, int k0) {
        const int k2_0 = k0 >> 1;
        const uint32_t so = (uint32_t)(st * STAGE);
        #pragma unroll
        for (int i = 0; i < 4; i++) {
            int c   = tid + i * 256;
            int row = c >> 3;
            int off = (c & 7) << 1;
            cp_async16(sbase + (so + row * ASTR + off) * 8,
                       A2 + (bm + row) * (size_t)K2 + k2_0 + off);
        }
        #pragma unroll
        for (int i = 0; i < BN / 32; i++) {
            int c  = tid + i * 256;
            int r  = c / (BN / 2);
            int cc = (c % (BN / 2)) << 1;
            cp_async16(sbase + (so + A_SZ + r * BSTR + cc) * 8,
                       B2 + (size_t)(k2_0 + r) * N + bn + cc);
        }
        asm volatile("cp.async.commit_group;" ::: "memory");
    };

    load_stage(0, 0);
    int stage = 0;

    for (int k0 = 0; k0 < K; k0 += 32) {
        const bool more = (k0 + 32) < K;
        if (more) load_stage(stage ^ 1, k0 + 32);
        if (more) asm volatile("cp.async.wait_group 1;" ::: "memory");
        else      asm volatile("cp.async.wait_group 0;" ::: "memory");
        __syncthreads();

        const uint2* As = usmem2 + stage * STAGE;
        const uint2* Bs = As + A_SZ;

        #pragma unroll
        for (int s = 0; s < 2; s++) {
            const int k2b = s * 8;
            uint32_t ah[MT][4], al[MT][4], bh[NT][2], bl[NT][2];
            #pragma unroll
            for (int mt = 0; mt < MT; mt++) {
                int m0 = mW + mt * 16 + gid;
                uint2 a0 = As[m0 * ASTR + k2b + tg];
                uint2 a1 = As[(m0 + 8) * ASTR + k2b + tg];
                uint2 a2 = As[m0 * ASTR + k2b + tg + 4];
                uint2 a3 = As[(m0 + 8) * ASTR + k2b + tg + 4];
                ah[mt][0] = a0.x; al[mt][0] = a0.y;
                ah[mt][1] = a1.x; al[mt][1] = a1.y;
                ah[mt][2] = a2.x; al[mt][2] = a2.y;
                ah[mt][3] = a3.x; al[mt][3] = a3.y;
            }
            #pragma unroll
            for (int nt = 0; nt < NT; nt++) {
                int n0 = nW + nt * 8 + gid;
                uint2 b0 = Bs[(k2b + tg) * BSTR + n0];
                uint2 b1 = Bs[(k2b + tg + 4) * BSTR + n0];
                bh[nt][0] = b0.x; bl[nt][0] = b0.y;
                bh[nt][1] = b1.x; bl[nt][1] = b1.y;
            }
            #pragma unroll
            for (int mt = 0; mt < MT; mt++)
                #pragma unroll
                for (int nt = 0; nt < NT; nt++) {
                    mma_bf16(acc[mt][nt], ah[mt], bh[nt]);
                    mma_bf16(acc[mt][nt], ah[mt], bl[nt]);
                    mma_bf16(acc[mt][nt], al[mt], bh[nt]);
                }
        }
        __syncthreads();
        stage ^= 1;
    }

    const int N2 = N >> 1;
    #pragma unroll
    for (int mt = 0; mt < MT; mt++) {
        size_t row0 = bm + mW + mt * 16 + gid;
        size_t row1 = row0 + 8;
        #pragma unroll
        for (int nt = 0; nt < NT; nt++) {
            int col = (int)bn + nW + nt * 8 + 2 * tg;
            float b0 = 0.f, b1 = 0.f;
            if (BIAS) { b0 = bias[col]; b1 = bias[col + 1]; }
            float v00 = acc[mt][nt][0] + b0, v01 = acc[mt][nt][1] + b1;
            float v10 = acc[mt][nt][2] + b0, v11 = acc[mt][nt][3] + b1;
            if (ACT == 1) {
                v00 = v00 / (1.f + expf(-v00));
                v01 = v01 / (1.f + expf(-v01));
                v10 = v10 / (1.f + expf(-v10));
                v11 = v11 / (1.f + expf(-v11));
            }
            if (OUT == 0) {
                *(float2*)(Cf + row0 * N + col) = make_float2(v00, v01);
                *(float2*)(Cf + row1 * N + col) = make_float2(v10, v11);
            } else {
                int hc = (col >> 1);
                uint32_t h, l;
                split_pack(v00, v01, h, l);
                C2[row0 * N2 + hc] = make_uint2(h, l);
                split_pack(v10, v11, h, l);
                C2[row1 * N2 + hc] = make_uint2(h, l);
            }
        }
    }
}

// ---------------- gate + fusion LN v4: 2 rows/warp, float2 (hi,lo) out ----------------
__global__ __launch_bounds__(256) void gate_fuse_v4(
    const float* __restrict__ sem, const float* __restrict__ col,
    const float* __restrict__ w1, const float* __restrict__ b1,
    const float* __restrict__ lng, const float* __restrict__ lnb,
    const float* __restrict__ w2, const float* __restrict__ b2,
    const float* __restrict__ flg, const float* __restrict__ flb,
    float* __restrict__ gate_out, float2* __restrict__ f2)
{
    extern __shared__ float sm[];
    float* w1s  = sm;
    float* w2s  = w1s + 64 * 128;
    float* b1s  = w2s + 128 * 64;
    float* lngs = b1s + 128;
    float* lnbs = lngs + 128;
    float* b2s  = lnbs + 128;
    float* flgs = b2s + 64;
    float* flbs = flgs + 832;

    const int tid  = threadIdx.x;
    const int lane = tid & 31;
    const int wid  = tid >> 5;

    for (int i = tid; i < 64 * 128; i += 256) w1s[i] = w1[i];
    for (int i = tid; i < 128 * 64; i += 256) w2s[i] = w2[i];
    if (tid < 128) { b1s[tid] = b1[tid]; lngs[tid] = lng[tid]; lnbs[tid] = lnb[tid]; }
    if (tid < 64)  b2s[tid] = b2[tid];
    for (int i = tid; i < 832; i += 256) { flgs[i] = flg[i]; flbs[i] = flb[i]; }
    __syncthreads();

    const int gwarp  = blockIdx.x * 8 + wid;
    const int nwarps = gridDim.x * 8;

    for (int base = 2 * gwarp; base < BATCH; base += 2 * nwarps) {
        const int rX = base, rY = base + 1;
        const float cX0 = col[(size_t)rX * 64 + lane];
        const float cX1 = col[(size_t)rX * 64 + 32 + lane];
        const float cY0 = col[(size_t)rY * 64 + lane];
        const float cY1 = col[(size_t)rY * 64 + 32 + lane];

        float hX[4], hY[4];
        #pragma unroll
        for (int t = 0; t < 4; t++) { hX[t] = b1s[lane + 32 * t]; hY[t] = hX[t]; }
        #pragma unroll
        for (int d = 0; d < 64; d++) {
            float vX = (d < 32) ? __shfl_sync(0xffffffffu, cX0, d)
                                : __shfl_sync(0xffffffffu, cX1, d - 32);
            float vY = (d < 32) ? __shfl_sync(0xffffffffu, cY0, d)
                                : __shfl_sync(0xffffffffu, cY1, d - 32);
            #pragma unroll
            for (int t = 0; t < 4; t++) {
                float w = w1s[d * 128 + lane + 32 * t];
                hX[t] += vX * w;
                hY[t] += vY * w;
            }
        }

        float sX = hX[0] + hX[1] + hX[2] + hX[3];
        float sY = hY[0] + hY[1] + hY[2] + hY[3];
        #pragma unroll
        for (int o = 16; o > 0; o >>= 1) {
            sX += __shfl_xor_sync(0xffffffffu, sX, o);
            sY += __shfl_xor_sync(0xffffffffu, sY, o);
        }
        float mX = sX * (1.f / 128.f), mY = sY * (1.f / 128.f);
        float vX = 0.f, vY = 0.f;
        #pragma unroll
        for (int t = 0; t < 4; t++) {
            float dX = hX[t] - mX; vX += dX * dX;
            float dY = hY[t] - mY; vY += dY * dY;
        }
        #pragma unroll
        for (int o = 16; o > 0; o >>= 1) {
            vX += __shfl_xor_sync(0xffffffffu, vX, o);
            vY += __shfl_xor_sync(0xffffffffu, vY, o);
        }
        float iX = rsqrtf(vX * (1.f / 128.f) + 1e-5f);
        float iY = rsqrtf(vY * (1.f / 128.f) + 1e-5f);
        #pragma unroll
        for (int t = 0; t < 4; t++) {
            float g = lngs[lane + 32 * t], bb = lnbs[lane + 32 * t];
            hX[t] = fmaxf((hX[t] - mX) * iX * g + bb, 0.f);
            hY[t] = fmaxf((hY[t] - mY) * iY * g + bb, 0.f);
        }

        float gX0 = b2s[lane], gX1 = b2s[lane + 32];
        float gY0 = gX0, gY1 = gX1;
        #pragma unroll
        for (int j = 0; j < 128; j++) {
            float hvX = __shfl_sync(0xffffffffu, hX[j >> 5], j & 31);
            float hvY = __shfl_sync(0xffffffffu, hY[j >> 5], j & 31);
            float wa = w2s[j * 64 + lane];
            float wb = w2s[j * 64 + lane + 32];
            gX0 += hvX * wa; gX1 += hvX * wb;
            gY0 += hvY * wa; gY1 += hvY * wb;
        }
        gX0 = 1.f / (1.f + expf(-gX0));
        gX1 = 1.f / (1.f + expf(-gX1));
        gY0 = 1.f / (1.f + expf(-gY0));
        gY1 = 1.f / (1.f + expf(-gY1));
        gate_out[(size_t)rX * 64 + lane]      = gX0;
        gate_out[(size_t)rX * 64 + 32 + lane] = gX1;
        gate_out[(size_t)rY * 64 + lane]      = gY0;
        gate_out[(size_t)rY * 64 + 32 + lane] = gY1;
        const float dX0 = gX0 * cX0, dX1 = gX1 * cX1;
        const float dY0 = gY0 * cY0, dY1 = gY1 * cY1;

        float svX[24], svY[24];
        const float* spX = sem + (size_t)rX * 768;
        const float* spY = sem + (size_t)rY * 768;
        float sumX = dX0 + dX1, sumY = dY0 + dY1;
        #pragma unroll
        for (int k = 0; k < 24; k++) {
            svX[k] = spX[lane + 32 * k]; sumX += svX[k];
            svY[k] = spY[lane + 32 * k]; sumY += svY[k];
        }
        #pragma unroll
        for (int o = 16; o > 0; o >>= 1) {
            sumX += __shfl_xor_sync(0xffffffffu, sumX, o);
            sumY += __shfl_xor_sync(0xffffffffu, sumY, o);
        }
        mX = sumX * (1.f / 832.f); mY = sumY * (1.f / 832.f);
        float varX = 0.f, varY = 0.f;
        { float d = dX0 - mX; varX += d * d; d = dX1 - mX; varX += d * d; }
        { float d = dY0 - mY; varY += d * d; d = dY1 - mY; varY += d * d; }
        #pragma unroll
        for (int k = 0; k < 24; k++) {
            float dXk = svX[k] - mX; varX += dXk * dXk;
            float dYk = svY[k] - mY; varY += dYk * dYk;
        }
        #pragma unroll
        for (int o = 16; o > 0; o >>= 1) {
            varX += __shfl_xor_sync(0xffffffffu, varX, o);
            varY += __shfl_xor_sync(0xffffffffu, varY, o);
        }
        iX = rsqrtf(varX * (1.f / 832.f) + 1e-5f);
        iY = rsqrtf(varY * (1.f / 832.f) + 1e-5f);

        float2* fX = f2 + (size_t)rX * 832;
        float2* fY = f2 + (size_t)rY * 832;
        #pragma unroll
        for (int k = 0; k < 24; k++) {
            int i = lane + 32 * k;
            float g = flgs[i], bb = flbs[i];
            float vfX = (svX[k] - mX) * iX * g + bb;
            float vfY = (svY[k] - mY) * iY * g + bb;
            float hvX = tf32_round(vfX), hvY = tf32_round(vfY);
            fX[i] = make_float2(hvX, vfX - hvX);
            fY[i] = make_float2(hvY, vfY - hvY);
        }
        {
            int i = 768 + lane;
            float g = flgs[i], bb = flbs[i];
            float vfX = (dX0 - mX) * iX * g + bb;
            float vfY = (dY0 - mY) * iY * g + bb;
            float hvX = tf32_round(vfX), hvY = tf32_round(vfY);
            fX[i] = make_float2(hvX, vfX - hvX);
            fY[i] = make_float2(hvY, vfY - hvY);
            i = 768 + 32 + lane;
            g = flgs[i]; bb = flbs[i];
            vfX = (dX1 - mX) * iX * g + bb;
            vfY = (dY1 - mY) * iY * g + bb;
            hvX = tf32_round(vfX); hvY = tf32_round(vfY);
            fX[i] = make_float2(hvX, vfX - hvX);
            fY[i] = make_float2(hvY, vfY - hvY);
        }
    }
}

// ---------------- residual quantization: warp-per-row ----------------
__global__ __launch_bounds__(256) void rq_warp_kernel(
    const float* __restrict__ cb,
    float* __restrict__ resid,
    float* __restrict__ zq,
    float* __restrict__ codes,
    uint2* __restrict__ zq2,
    int layer)
{
    extern __shared__ float cbs[];  // 256*65
    __shared__ float cbn[256];
    __shared__ float blk[256];

    const int tid  = threadIdx.x;
    const int lane = tid & 31;
    const int wid  = tid >> 5;

    for (int i = tid; i < 256 * 64; i += 256) {
        int c = i >> 6, d = i & 63;
        cbs[c * 65 + d] = cb[i];
    }
    __syncthreads();
    {
        float nv = 0.f;
        #pragma unroll 16
        for (int d = 0; d < 64; d++) { float v = cbs[tid * 65 + d]; nv += v * v; }
        cbn[tid] = 0.5f * nv;
    }
    __syncthreads();

    const int gwarp  = blockIdx.x * 8 + wid;
    const int nwarps = gridDim.x * 8;
    float lossAcc = 0.f;

    for (int base = 2 * gwarp; base < BATCH; base += 2 * nwarps) {
        const int rowA = base, rowB = base + 1;
        float a0 = resid[(size_t)rowA * 64 + lane];
        float a1 = resid[(size_t)rowA * 64 + 32 + lane];
        float b0 = resid[(size_t)rowB * 64 + lane];
        float b1 = resid[(size_t)rowB * 64 + 32 + lane];

        float sa = a0 * a0 + a1 * a1;
        float sb = b0 * b0 + b1 * b1;
        #pragma unroll
        for (int o = 16; o > 0; o >>= 1) {
            sa += __shfl_xor_sync(0xffffffffu, sa, o);
            sb += __shfl_xor_sync(0xffffffffu, sb, o);
        }
        sa = __shfl_sync(0xffffffffu, sa, 0);
        sb = __shfl_sync(0xffffffffu, sb, 0);
        float invA = 1.f / fmaxf(sqrtf(sa), 1e-12f);
        float invB = 1.f / fmaxf(sqrtf(sb), 1e-12f);
        a0 *= invA; a1 *= invA;
        b0 *= invB; b1 *= invB;

        float accA[8], accB[8];
        #pragma unroll
        for (int j = 0; j < 8; j++) {
            float n = cbn[lane + 32 * j];
            accA[j] = -n; accB[j] = -n;
        }
        #pragma unroll 8
        for (int d = 0; d < 64; d++) {
            float ra = (d < 32) ? __shfl_sync(0xffffffffu, a0, d)
                                : __shfl_sync(0xffffffffu, a1, d - 32);
            float rb = (d < 32) ? __shfl_sync(0xffffffffu, b0, d)
                                : __shfl_sync(0xffffffffu, b1, d - 32);
            #pragma unroll
            for (int j = 0; j < 8; j++) {
                float w = cbs[(lane + 32 * j) * 65 + d];
                accA[j] += ra * w;
                accB[j] += rb * w;
            }
        }

        float bvA = accA[0], bvB = accB[0];
        int   bcA = lane,    bcB = lane;
        #pragma unroll
        for (int j = 1; j < 8; j++) {
            int c = lane + 32 * j;
            if (accA[j] > bvA) { bvA = accA[j]; bcA = c; }
            if (accB[j] > bvB) { bvB = accB[j]; bcB = c; }
        }
        #pragma unroll
        for (int o = 16; o > 0; o >>= 1) {
            float ovA = __shfl_xor_sync(0xffffffffu, bvA, o);
            int   ocA = __shfl_xor_sync(0xffffffffu, bcA, o);
            if (ovA > bvA || (ovA == bvA && ocA < bcA)) { bvA = ovA; bcA = ocA; }
            float ovB = __shfl_xor_sync(0xffffffffu, bvB, o);
            int   ocB = __shfl_xor_sync(0xffffffffu, bcB, o);
            if (ovB > bvB || (ovB == bvB && ocB < bcB)) { bvB = ovB; bcB = ocB; }
        }

        float eA0 = cbs[bcA * 65 + lane], eA1 = cbs[bcA * 65 + 32 + lane];
        float eB0 = cbs[bcB * 65 + lane], eB1 = cbs[bcB * 65 + 32 + lane];

        size_t oA = (size_t)rowA * 64 + lane, oB = (size_t)rowB * 64 + lane;
        float zA0, zA1, zB0, zB1;
        if (layer == 0) { zA0 = eA0; zA1 = eA1; zB0 = eB0; zB1 = eB1; }
        else {
            zA0 = zq[oA] + eA0; zA1 = zq[oA + 32] + eA1;
            zB0 = zq[oB] + eB0; zB1 = zq[oB + 32] + eB1;
        }
        zq[oA] = zA0; zq[oA + 32] = zA1;
        zq[oB] = zB0; zq[oB + 32] = zB1;
        resid[oA] = a0 - eA0; resid[oA + 32] = a1 - eA1;
        resid[oB] = b0 - eB0; resid[oB + 32] = b1 - eB1;
        {
            float d;
            d = eA0 - a0; lossAcc += d * d;
            d = eA1 - a1; lossAcc += d * d;
            d = eB0 - b0; lossAcc += d * d;
            d = eB1 - b1; lossAcc += d * d;
        }
        if (lane == 0) {
            codes[(size_t)rowA * 3 + layer] = (float)bcA;
            codes[(size_t)rowB * 3 + layer] = (float)bcB;
        }

        if (layer == 2) {
            const int i0 = (2 * lane) & 31;
            const int i1 = (2 * lane + 1) & 31;
            float s0A = __shfl_sync(0xffffffffu, zA0, i0);
            float s1A = __shfl_sync(0xffffffffu, zA1, i0);
            float t0A = __shfl_sync(0xffffffffu, zA0, i1);
            float t1A = __shfl_sync(0xffffffffu, zA1, i1);
            float s0B = __shfl_sync(0xffffffffu, zB0, i0);
            float s1B = __shfl_sync(0xffffffffu, zB1, i0);
            float t0B = __shfl_sync(0xffffffffu, zB0, i1);
            float t1B = __shfl_sync(0xffffffffu, zB1, i1);
            float zaA = (lane < 16) ? s0A : s1A;
            float zbA = (lane < 16) ? t0A : t1A;
            float zaB = (lane < 16) ? s0B : s1B;
            float zbB = (lane < 16) ? t0B : t1B;
            uint32_t h, l;
            split_pack(zaA, zbA, h, l);
            zq2[(size_t)rowA * 32 + lane] = make_uint2(h, l);
            split_pack(zaB, zbB, h, l);
            zq2[(size_t)rowB * 32 + lane] = make_uint2(h, l);
        }
    }

    blk[tid] = lossAcc; __syncthreads();
    for (int st = 128; st > 0; st >>= 1) { if (tid < st) blk[tid] += blk[tid + st]; __syncthreads(); }
    if (tid == 0) atomicAdd(&g_loss, (double)blk[0]);
}

// ---------------- row LN + ReLU -> bf16 pair uint2 ----------------
template<int W, int T>
__global__ __launch_bounds__(T) void ln_pair(
    const float* __restrict__ in, const float* __restrict__ g,
    const float* __restrict__ b, uint2* __restrict__ o2)
{
    constexpr int J  = W / (2 * T);
    constexpr int NW = T / 32;
    __shared__ float red[NW];
    __shared__ float s_m, s_i;
    const int tid = threadIdx.x, lane = tid & 31, wid = tid >> 5;

    for (int row = blockIdx.x; row < BATCH; row += gridDim.x) {
        const float2* ip = (const float2*)(in + (size_t)row * W);
        float2 x[J];
        float s = 0.f;
        #pragma unroll
        for (int j = 0; j < J; j++) { x[j] = ip[tid + T * j]; s += x[j].x + x[j].y; }
        #pragma unroll
        for (int o = 16; o > 0; o >>= 1) s += __shfl_xor_sync(0xffffffffu, s, o);
        if (lane == 0) red[wid] = s;
        __syncthreads();
        if (tid < 32) {
            float v = (tid < NW) ? red[tid] : 0.f;
            #pragma unroll
            for (int o = NW / 2; o > 0; o >>= 1) v += __shfl_xor_sync(0xffffffffu, v, o);
            if (tid == 0) s_m = v * (1.f / (float)W);
        }
        __syncthreads();
        float m = s_m, v2 = 0.f;
        #pragma unroll
        for (int j = 0; j < J; j++) {
            float d0 = x[j].x - m, d1 = x[j].y - m;
            v2 += d0 * d0 + d1 * d1;
        }
        #pragma unroll
        for (int o = 16; o > 0; o >>= 1) v2 += __shfl_xor_sync(0xffffffffu, v2, o);
        if (lane == 0) red[wid] = v2;
        __syncthreads();
        if (tid < 32) {
            float v = (tid < NW) ? red[tid] : 0.f;
            #pragma unroll
            for (int o = NW / 2; o > 0; o >>= 1) v += __shfl_xor_sync(0xffffffffu, v, o);
            if (tid == 0) s_i = rsqrtf(v * (1.f / (float)W) + 1e-5f);
        }
        __syncthreads();
        float inv = s_i;
        uint2* op = o2 + (size_t)row * (W / 2);
        #pragma unroll
        for (int j = 0; j < J; j++) {
            int p = tid + T * j;
            float2 gg = *(const float2*)(g + 2 * p);
            float2 bb = *(const float2*)(b + 2 * p);
            float v0 = fmaxf((x[j].x - m) * inv * gg.x + bb.x, 0.f);
            float v1 = fmaxf((x[j].y - m) * inv * gg.y + bb.y, 0.f);
            uint32_t h, l;
            split_pack(v0, v1, h, l);
            op[p] = make_uint2(h, l);
        }
        __syncthreads();
    }
}

// ---------------- host ----------------
extern "C" void kernel_launch(void* const* d_in, const int* in_sizes, int n_in,
                              void* d_out, int out_size)
{
    (void)in_sizes; (void)n_in; (void)out_size;
    const float* sem_emb  = (const float*)d_in[0];
    const float* col_emb  = (const float*)d_in[1];
    const float* gate_w1  = (const float*)d_in[2];
    const float* gate_b1  = (const float*)d_in[3];
    const float* gate_lng = (const float*)d_in[4];
    const float* gate_lnb = (const float*)d_in[5];
    const float* gate_w2  = (const float*)d_in[6];
    const float* gate_b2  = (const float*)d_in[7];
    const float* fus_lng  = (const float*)d_in[8];
    const float* fus_lnb  = (const float*)d_in[9];
    const float* enc_w1   = (const float*)d_in[10];
    const float* enc_w2   = (const float*)d_in[11];
    const float* enc_w3   = (const float*)d_in[12];
    const float* enc_w4   = (const float*)d_in[13];
    const float* dec_w1   = (const float*)d_in[14];
    const float* dec_w2   = (const float*)d_in[15];
    const float* dec_w3   = (const float*)d_in[16];
    const float* sem_w1   = (const float*)d_in[17];
    const float* sem_b1   = (const float*)d_in[18];
    const float* sem_lng  = (const float*)d_in[19];
    const float* sem_lnb  = (const float*)d_in[20];
    const float* sem_w2   = (const float*)d_in[21];
    const float* sem_b2   = (const float*)d_in[22];
    const float* col_w1   = (const float*)d_in[23];
    const float* col_b1   = (const float*)d_in[24];
    const float* col_lng  = (const float*)d_in[25];
    const float* col_lnb  = (const float*)d_in[26];
    const float* col_w2   = (const float*)d_in[27];
    const float* col_b2   = (const float*)d_in[28];
    const float* codebooks= (const float*)d_in[29];

    float* out = (float*)d_out;
    const size_t B = BATCH;
    float* o_sem   = out;
    float* o_col   = o_sem + B * 768;
    float* o_zq    = o_col + B * 64;
    float* o_codes = o_zq + B * 64;
    float* o_loss  = o_codes + B * 3;
    float* o_gate  = o_loss + 2;

    float *p_res, *p_hh, *p_chh;
    float2 *p_f2, *p_z12, *p_z22, *p_z32, *p_ew2;
    cudaGetSymbolAddress((void**)&p_res, g_res);
    cudaGetSymbolAddress((void**)&p_hh,  g_hh);
    cudaGetSymbolAddress((void**)&p_chh, g_chh);
    cudaGetSymbolAddress((void**)&p_f2,  g_f2);
    cudaGetSymbolAddress((void**)&p_z12, g_z12);
    cudaGetSymbolAddress((void**)&p_z22, g_z22);
    cudaGetSymbolAddress((void**)&p_z32, g_z32);
    cudaGetSymbolAddress((void**)&p_ew2, g_ew2);

    uint2 *p_zq2, *p_s12, *p_s22, *p_s32, *p_hl2, *p_ch2, *p_w2;
    cudaGetSymbolAddress((void**)&p_zq2, g_zq2);
    cudaGetSymbolAddress((void**)&p_s12, g_s12);
    cudaGetSymbolAddress((void**)&p_s22, g_s22);
    cudaGetSymbolAddress((void**)&p_s32, g_s32);
    cudaGetSymbolAddress((void**)&p_hl2, g_hl2);
    cudaGetSymbolAddress((void**)&p_ch2, g_ch2);
    cudaGetSymbolAddress((void**)&p_w2,  g_w2);

    const int EW1 = 0, EW2 = 425984, EW3 = 557056, EW4 = 589824;
    const int OFF_DEC1 = 0, OFF_DEC2 = 4096, OFF_DEC3 = 20480, OFF_SEM1 = 86016;
    const int OFF_SEM2 = 479232, OFF_COL1 = 1069056, OFF_COL2 = 1134592;

    const int GATE_SMEM  = (64*128 + 128*64 + 128*3 + 64 + 832*2) * 4;
    const int RQ_SMEM    = 256 * 65 * 4;
    const int SMEM_128 = 2 * (2560 + 16 * 132) * 8;  // 74752 B (float2/uint2 units)
    const int SMEM_64  = 2 * (2560 + 16 * 68)  * 8;  // 58368 B
    cudaFuncSetAttribute(gate_fuse_v4,   cudaFuncAttributeMaxDynamicSharedMemorySize, GATE_SMEM);
    cudaFuncSetAttribute(rq_warp_kernel, cudaFuncAttributeMaxDynamicSharedMemorySize, RQ_SMEM);
    cudaFuncSetAttribute(gemm_tf32_pre<128, 1, 1>, cudaFuncAttributeMaxDynamicSharedMemorySize, SMEM_128);
    cudaFuncSetAttribute(gemm_tf32_pre<64,  0, 0>, cudaFuncAttributeMaxDynamicSharedMemorySize, SMEM_64);
    cudaFuncSetAttribute(gemm_bf16x3<128, 1, false, 1>, cudaFuncAttributeMaxDynamicSharedMemorySize, SMEM_128);
    cudaFuncSetAttribute(gemm_bf16x3<128, 0, true,  0>, cudaFuncAttributeMaxDynamicSharedMemorySize, SMEM_128);
    cudaFuncSetAttribute(gemm_bf16x3<64,  0, true,  0>, cudaFuncAttributeMaxDynamicSharedMemorySize, SMEM_64);

    // launch order: 1 pack_enc, 2 pack_dec, 3 gate, 4 enc1 (ncu target), 5 zero_loss, ...
    pack_enc_tf32<<<512, 256>>>(enc_w1, enc_w2, enc_w3, enc_w4, p_ew2);
    pack_dec_bf16<<<512, 256>>>(dec_w1, dec_w2, dec_w3, sem_w1, sem_w2, col_w1, col_w2, p_w2);

    gate_fuse_v4<<<2048, 256, GATE_SMEM>>>(
        sem_emb, col_emb, gate_w1, gate_b1, gate_lng, gate_lnb,
        gate_w2, gate_b2, fus_lng, fus_lnb, o_gate, p_f2);

    gemm_tf32_pre<128, 1, 1><<<dim3(4, 512), 256, SMEM_128>>>(
        p_f2, p_ew2 + EW1, nullptr, p_z12, BATCH, 512, 832);

    zero_loss_kernel<<<1, 1>>>();

    gemm_tf32_pre<128, 1, 1><<<dim3(2, 512), 256, SMEM_128>>>(
        p_z12, p_ew2 + EW2, nullptr, p_z22, BATCH, 256, 512);
    gemm_tf32_pre<128, 1, 1><<<dim3(1, 512), 256, SMEM_128>>>(
        p_z22, p_ew2 + EW3, nullptr, p_z32, BATCH, 128, 256);
    gemm_tf32_pre<64, 0, 0><<<dim3(1, 512), 256, SMEM_64>>>(
        p_z32, p_ew2 + EW4, p_res, nullptr, BATCH, 64, 128);

    for (int l = 0; l < 3; l++)
        rq_warp_kernel<<<1024, 256, RQ_SMEM>>>(
            codebooks + (size_t)l * 256 * 64, p_res, o_zq, o_codes, p_zq2, l);
    finalize_kernel<<<1, 1>>>(o_loss);

    gemm_bf16x3<128, 1, false, 1><<<dim3(1, 512), 256, SMEM_128>>>(
        p_zq2, p_w2 + OFF_DEC1, nullptr, nullptr, p_s12, BATCH, 128, 64);
    gemm_bf16x3<128, 1, false, 1><<<dim3(2, 512), 256, SMEM_128>>>(
        p_s12, p_w2 + OFF_DEC2, nullptr, nullptr, p_s22, BATCH, 256, 128);
    gemm_bf16x3<128, 1, false, 1><<<dim3(4, 512), 256, SMEM_128>>>(
        p_s22, p_w2 + OFF_DEC3, nullptr, nullptr, p_s32, BATCH, 512, 256);

    gemm_bf16x3<128, 0, true, 0><<<dim3(12, 512), 256, SMEM_128>>>(
        p_s32, p_w2 + OFF_SEM1, sem_b1, p_hh, nullptr, BATCH, 1536, 512);
    ln_pair<1536, 256><<<8192, 256>>>(p_hh, sem_lng, sem_lnb, p_hl2);
    gemm_bf16x3<128, 0, true, 0><<<dim3(6, 512), 256, SMEM_128>>>(
        p_hl2, p_w2 + OFF_SEM2, sem_b2, o_sem, nullptr, BATCH, 768, 1536);

    gemm_bf16x3<128, 0, true, 0><<<dim3(2, 512), 256, SMEM_128>>>(
        p_s32, p_w2 + OFF_COL1, col_b1, p_chh, nullptr, BATCH, 256, 512);
    ln_pair<256, 128><<<8192, 128>>>(p_chh, col_lng, col_lnb, p_ch2);
    gemm_bf16x3<64, 0, true, 0><<<dim3(1, 512), 256, SMEM_64>>>(
        p_ch2, p_w2 + OFF_COL2, col_b2, o_col, nullptr, BATCH, 64, 256);
}

// round 13
// speedup vs baseline: 1.1019x; 1.1019x over previous
#include <cuda_runtime.h>
#include <cuda_bf16.h>
#include <math.h>
#include <stdint.h>

#define BATCH 65536

// ---------------- scratch ----------------
__device__ float g_res[(size_t)BATCH * 64];
__device__ float g_hh[(size_t)BATCH * 1536];
__device__ float g_chh[(size_t)BATCH * 256];
__device__ double g_loss;

// tf32 hi/lo activation buffers (fp32 storage)
__device__ float g_fh[(size_t)BATCH * 832],  g_fl[(size_t)BATCH * 832];
__device__ float g_z1h[(size_t)BATCH * 512], g_z1l[(size_t)BATCH * 512];
__device__ float g_z2h[(size_t)BATCH * 256], g_z2l[(size_t)BATCH * 256];
__device__ float g_z3h[(size_t)BATCH * 128], g_z3l[(size_t)BATCH * 128];
// tf32 hi/lo encoder weights
__device__ float g_ewh[598016], g_ewl[598016];

// bf16 pair activation buffers: [B][K/2] u32
__device__ uint32_t g_zqh[(size_t)BATCH * 32],  g_zql[(size_t)BATCH * 32];
__device__ uint32_t g_s1h[(size_t)BATCH * 64],  g_s1l[(size_t)BATCH * 64];
__device__ uint32_t g_s2h[(size_t)BATCH * 128], g_s2l[(size_t)BATCH * 128];
__device__ uint32_t g_s3h[(size_t)BATCH * 256], g_s3l[(size_t)BATCH * 256];
__device__ uint32_t g_hlh[(size_t)BATCH * 768], g_hll[(size_t)BATCH * 768];
__device__ uint32_t g_chl[(size_t)BATCH * 128], g_cll[(size_t)BATCH * 128];
// bf16 pair packed dec/head weights
__device__ uint32_t g_whi[1142784], g_wlo[1142784];

__global__ void zero_loss_kernel() { g_loss = 0.0; }

__global__ void finalize_kernel(float* out_loss) {
    float v = (float)(g_loss / ((double)BATCH * 64.0));
    out_loss[0] = v;
    out_loss[1] = v;
}

// ---------------- helpers ----------------
__device__ __forceinline__ float tf32_round(float x) {
    uint32_t r;
    asm("cvt.rna.tf32.f32 %0, %1;" : "=r"(r) : "f"(x));
    return __uint_as_float(r);
}

__device__ __forceinline__ void mma_tf32(float* d, const uint32_t* a, const uint32_t* b) {
    asm volatile(
        "mma.sync.aligned.m16n8k8.row.col.f32.tf32.tf32.f32 "
        "{%0,%1,%2,%3}, {%4,%5,%6,%7}, {%8,%9}, {%0,%1,%2,%3};"
        : "+f"(d[0]), "+f"(d[1]), "+f"(d[2]), "+f"(d[3])
        : "r"(a[0]), "r"(a[1]), "r"(a[2]), "r"(a[3]), "r"(b[0]), "r"(b[1]));
}

__device__ __forceinline__ void mma_bf16(float* d, const uint32_t* a, const uint32_t* b) {
    asm volatile(
        "mma.sync.aligned.m16n8k16.row.col.f32.bf16.bf16.f32 "
        "{%0,%1,%2,%3}, {%4,%5,%6,%7}, {%8,%9}, {%0,%1,%2,%3};"
        : "+f"(d[0]), "+f"(d[1]), "+f"(d[2]), "+f"(d[3])
        : "r"(a[0]), "r"(a[1]), "r"(a[2]), "r"(a[3]), "r"(b[0]), "r"(b[1]));
}

__device__ __forceinline__ void split_pack(float x0, float x1, uint32_t& hi, uint32_t& lo) {
    __nv_bfloat16 h0 = __float2bfloat16_rn(x0);
    __nv_bfloat16 h1 = __float2bfloat16_rn(x1);
    __nv_bfloat16 l0 = __float2bfloat16_rn(x0 - __bfloat162float(h0));
    __nv_bfloat16 l1 = __float2bfloat16_rn(x1 - __bfloat162float(h1));
    hi = ((uint32_t)__bfloat16_as_ushort(h1) << 16) | (uint32_t)__bfloat16_as_ushort(h0);
    lo = ((uint32_t)__bfloat16_as_ushort(l1) << 16) | (uint32_t)__bfloat16_as_ushort(l0);
}

__device__ __forceinline__ void cp_async16(uint32_t dst, const void* src) {
    asm volatile("cp.async.cg.shared.global [%0], [%1], 16;" :: "r"(dst), "l"(src));
}

__device__ __forceinline__ uint32_t smem_u32(const void* p) {
    uint32_t a;
    asm("{ .reg .u64 t; cvta.to.shared.u64 t, %1; cvt.u32.u64 %0, t; }" : "=r"(a) : "l"(p));
    return a;
}

// ---------------- pack kernels ----------------
__global__ void pack_enc_tf32(const float* __restrict__ w1, const float* __restrict__ w2,
                              const float* __restrict__ w3, const float* __restrict__ w4,
                              float* __restrict__ wh, float* __restrict__ wl)
{
    for (int i = blockIdx.x * blockDim.x + threadIdx.x; i < 598016; i += gridDim.x * blockDim.x) {
        float x;
        if      (i < 425984) x = w1[i];
        else if (i < 557056) x = w2[i - 425984];
        else if (i < 589824) x = w3[i - 557056];
        else                 x = w4[i - 589824];
        float h = tf32_round(x);
        wh[i] = h; wl[i] = x - h;
    }
}

__global__ void pack_dec_bf16(const float* __restrict__ d1, const float* __restrict__ d2,
                              const float* __restrict__ d3, const float* __restrict__ s1,
                              const float* __restrict__ s2, const float* __restrict__ c1,
                              const float* __restrict__ c2,
                              uint32_t* __restrict__ wh, uint32_t* __restrict__ wl)
{
    for (int i = blockIdx.x * blockDim.x + threadIdx.x; i < 1142784; i += gridDim.x * blockDim.x) {
        const float* W; int li, N;
        if      (i < 4096)    { W = d1; li = i;           N = 128;  }
        else if (i < 20480)   { W = d2; li = i - 4096;    N = 256;  }
        else if (i < 86016)   { W = d3; li = i - 20480;   N = 512;  }
        else if (i < 479232)  { W = s1; li = i - 86016;   N = 1536; }
        else if (i < 1069056) { W = s2; li = i - 479232;  N = 768;  }
        else if (i < 1134592) { W = c1; li = i - 1069056; N = 256;  }
        else                  { W = c2; li = i - 1134592; N = 64;   }
        int k2 = li / N, n = li - k2 * N;
        float x0 = W[(size_t)(2 * k2) * N + n];
        float x1 = W[(size_t)(2 * k2 + 1) * N + n];
        uint32_t h, l;
        split_pack(x0, x1, h, l);
        wh[i] = h; wl[i] = l;
    }
}

// ---------------- tf32-3x GEMM, pre-split inputs, cp.async 2-stage, 1 sync/iter ----------------
template<int BN, int ACT, int OUT>
__global__ __launch_bounds__(256, 2) void gemm_tf32_pre(
    const float* __restrict__ Ah_, const float* __restrict__ Al_,
    const float* __restrict__ Bh_, const float* __restrict__ Bl_,
    float* __restrict__ Cf, float* __restrict__ Chi, float* __restrict__ Clo,
    int M, int N, int K)
{
    constexpr int ASTR = 20;
    constexpr int A_SZ = 128 * ASTR;
    constexpr int BSTR = BN + 8;
    constexpr int B_SZ = 16 * BSTR;
    constexpr int STAGE = 2 * A_SZ + 2 * B_SZ;
    constexpr int MT = 4;
    constexpr int NT = BN / 32;

    extern __shared__ float smem[];
    const uint32_t sbase = smem_u32(smem);

    const int tid  = threadIdx.x;
    const int warp = tid >> 5;
    const int lane = tid & 31;
    const int gid  = lane >> 2;
    const int tg   = lane & 3;
    const int mW   = (warp & 1) * 64;
    const int nW   = (warp >> 1) * (BN / 4);

    const size_t bm = (size_t)blockIdx.y * 128;
    const size_t bn = (size_t)blockIdx.x * BN;

    float acc[MT][NT][4];
    #pragma unroll
    for (int i = 0; i < MT; i++)
        #pragma unroll
        for (int j = 0; j < NT; j++)
            #pragma unroll
            for (int r = 0; r < 4; r++) acc[i][j][r] = 0.f;

    const int rowA = tid >> 2;
    const int ccA  = (tid & 3) << 2;

    auto load_stage = [&](int st, int k0) {
        const uint32_t so = (uint32_t)(st * STAGE);
        #pragma unroll
        for (int i = 0; i < 2; i++) {
            int r = rowA + i * 64;
            cp_async16(sbase + (so + r * ASTR + ccA) * 4, Ah_ + (bm + r) * (size_t)K + k0 + ccA);
            cp_async16(sbase + (so + A_SZ + r * ASTR + ccA) * 4, Al_ + (bm + r) * (size_t)K + k0 + ccA);
        }
        #pragma unroll
        for (int i = 0; i < BN / 64; i++) {
            int c  = tid + i * 256;
            int r  = c / (BN / 4);
            int cc = (c % (BN / 4)) << 2;
            cp_async16(sbase + (so + 2 * A_SZ + r * BSTR + cc) * 4, Bh_ + (size_t)(k0 + r) * N + bn + cc);
            cp_async16(sbase + (so + 2 * A_SZ + B_SZ + r * BSTR + cc) * 4, Bl_ + (size_t)(k0 + r) * N + bn + cc);
        }
        asm volatile("cp.async.commit_group;" ::: "memory");
    };

    load_stage(0, 0);
    int stage = 0;

    for (int k0 = 0; k0 < K; k0 += 16) {
        // wait for current tile, barrier, THEN issue next load (overlaps compute below)
        asm volatile("cp.async.wait_group 0;" ::: "memory");
        __syncthreads();
        const bool more = (k0 + 16) < K;
        if (more) load_stage(stage ^ 1, k0 + 16);

        const float* As_h = smem + stage * STAGE;
        const float* As_l = As_h + A_SZ;
        const float* Bs_h = As_l + A_SZ;
        const float* Bs_l = Bs_h + B_SZ;

        #pragma unroll
        for (int kk = 0; kk < 16; kk += 8) {
            uint32_t ah[MT][4], al[MT][4], bh[NT][2], bl[NT][2];
            #pragma unroll
            for (int mt = 0; mt < MT; mt++) {
                int m0 = mW + mt * 16 + gid;
                ah[mt][0] = __float_as_uint(As_h[m0 * ASTR + kk + tg]);
                ah[mt][1] = __float_as_uint(As_h[(m0 + 8) * ASTR + kk + tg]);
                ah[mt][2] = __float_as_uint(As_h[m0 * ASTR + kk + tg + 4]);
                ah[mt][3] = __float_as_uint(As_h[(m0 + 8) * ASTR + kk + tg + 4]);
                al[mt][0] = __float_as_uint(As_l[m0 * ASTR + kk + tg]);
                al[mt][1] = __float_as_uint(As_l[(m0 + 8) * ASTR + kk + tg]);
                al[mt][2] = __float_as_uint(As_l[m0 * ASTR + kk + tg + 4]);
                al[mt][3] = __float_as_uint(As_l[(m0 + 8) * ASTR + kk + tg + 4]);
            }
            #pragma unroll
            for (int nt = 0; nt < NT; nt++) {
                int n0 = nW + nt * 8 + gid;
                bh[nt][0] = __float_as_uint(Bs_h[(kk + tg) * BSTR + n0]);
                bh[nt][1] = __float_as_uint(Bs_h[(kk + tg + 4) * BSTR + n0]);
                bl[nt][0] = __float_as_uint(Bs_l[(kk + tg) * BSTR + n0]);
                bl[nt][1] = __float_as_uint(Bs_l[(kk + tg + 4) * BSTR + n0]);
            }
            #pragma unroll
            for (int mt = 0; mt < MT; mt++)
                #pragma unroll
                for (int nt = 0; nt < NT; nt++) {
                    mma_tf32(acc[mt][nt], al[mt], bh[nt]);
                    mma_tf32(acc[mt][nt], ah[mt], bl[nt]);
                    mma_tf32(acc[mt][nt], ah[mt], bh[nt]);
                }
        }
        stage ^= 1;
    }

    #pragma unroll
    for (int mt = 0; mt < MT; mt++) {
        size_t row0 = bm + mW + mt * 16 + gid;
        size_t row1 = row0 + 8;
        #pragma unroll
        for (int nt = 0; nt < NT; nt++) {
            int col = (int)bn + nW + nt * 8 + 2 * tg;
            float v00 = acc[mt][nt][0], v01 = acc[mt][nt][1];
            float v10 = acc[mt][nt][2], v11 = acc[mt][nt][3];
            if (ACT == 1) {
                v00 = v00 / (1.f + expf(-v00));
                v01 = v01 / (1.f + expf(-v01));
                v10 = v10 / (1.f + expf(-v10));
                v11 = v11 / (1.f + expf(-v11));
            }
            if (OUT == 0) {
                *(float2*)(Cf + row0 * N + col) = make_float2(v00, v01);
                *(float2*)(Cf + row1 * N + col) = make_float2(v10, v11);
            } else {
                float h00 = tf32_round(v00), h01 = tf32_round(v01);
                float h10 = tf32_round(v10), h11 = tf32_round(v11);
                *(float2*)(Chi + row0 * N + col) = make_float2(h00, h01);
                *(float2*)(Clo + row0 * N + col) = make_float2(v00 - h00, v01 - h01);
                *(float2*)(Chi + row1 * N + col) = make_float2(h10, h11);
                *(float2*)(Clo + row1 * N + col) = make_float2(v10 - h10, v11 - h11);
            }
        }
    }
}

// ---------------- bf16x3 GEMM (dec/heads), 1 sync/iter ----------------
template<int BN, int ACT, bool BIAS, int OUT>
__global__ __launch_bounds__(256, 2) void gemm_bf16x3(
    const uint32_t* __restrict__ Ahi, const uint32_t* __restrict__ Alo,
    const uint32_t* __restrict__ Bh,  const uint32_t* __restrict__ Bl,
    const float* __restrict__ bias,
    float* __restrict__ Cf, uint32_t* __restrict__ Chi, uint32_t* __restrict__ Clo,
    int M, int N, int K)
{
    constexpr int ASTRIDE = 20;
    constexpr int A_SZ = 128 * ASTRIDE;
    constexpr int BSTRIDE = BN + 8;
    constexpr int B_SZ = 16 * BSTRIDE;
    constexpr int STAGE = 2 * A_SZ + 2 * B_SZ;
    constexpr int MT = 4;
    constexpr int NT = BN / 32;

    extern __shared__ uint32_t usmem[];
    const uint32_t sbase = smem_u32(usmem);

    const int tid  = threadIdx.x;
    const int warp = tid >> 5;
    const int lane = tid & 31;
    const int gid  = lane >> 2;
    const int tg   = lane & 3;
    const int mW   = (warp & 1) * 64;
    const int nW   = (warp >> 1) * (BN / 4);

    const size_t bm = (size_t)blockIdx.y * 128;
    const size_t bn = (size_t)blockIdx.x * BN;
    const int K2 = K >> 1;
    const uint32_t* Bhb = Bh + bn;
    const uint32_t* Blb = Bl + bn;

    float acc[MT][NT][4];
    #pragma unroll
    for (int i = 0; i < MT; i++)
        #pragma unroll
        for (int j = 0; j < NT; j++)
            #pragma unroll
            for (int r = 0; r < 4; r++) acc[i][j][r] = 0.f;

    const int rowA = tid >> 2;
    const int ccA  = (tid & 3) << 2;

    auto load_stage = [&](int st, int k0) {
        const int k2_0 = k0 >> 1;
        const uint32_t so = (uint32_t)(st * STAGE);
        #pragma unroll
        for (int i = 0; i < 2; i++) {
            int r = rowA + i * 64;
            cp_async16(sbase + (so + r * ASTRIDE + ccA) * 4, Ahi + (bm + r) * (size_t)K2 + k2_0 + ccA);
            cp_async16(sbase + (so + A_SZ + r * ASTRIDE + ccA) * 4, Alo + (bm + r) * (size_t)K2 + k2_0 + ccA);
        }
        #pragma unroll
        for (int i = 0; i < BN / 64; i++) {
            int c  = tid + i * 256;
            int r  = c / (BN / 4);
            int cc = (c % (BN / 4)) << 2;
            cp_async16(sbase + (so + 2 * A_SZ + r * BSTRIDE + cc) * 4, Bhb + (size_t)(k2_0 + r) * N + cc);
            cp_async16(sbase + (so + 2 * A_SZ + B_SZ + r * BSTRIDE + cc) * 4, Blb + (size_t)(k2_0 + r) * N + cc);
        }
        asm volatile("cp.async.commit_group;" ::: "memory");
    };

    load_stage(0, 0);
    int stage = 0;

    for (int k0 = 0; k0 < K; k0 += 32) {
        asm volatile("cp.async.wait_group 0;" ::: "memory");
        __syncthreads();
        const bool more = (k0 + 32) < K;
        if (more) load_stage(stage ^ 1, k0 + 32);

        const uint32_t* As_h = usmem + stage * STAGE;
        const uint32_t* As_l = As_h + A_SZ;
        const uint32_t* Bs_h = As_l + A_SZ;
        const uint32_t* Bs_l = Bs_h + B_SZ;

        #pragma unroll
        for (int s = 0; s < 2; s++) {
            const int k2b = s * 8;
            uint32_t ah[MT][4], al[MT][4], bh[NT][2], bl[NT][2];
            #pragma unroll
            for (int mt = 0; mt < MT; mt++) {
                int m0 = mW + mt * 16 + gid;
                ah[mt][0] = As_h[m0 * ASTRIDE + k2b + tg];
                ah[mt][1] = As_h[(m0 + 8) * ASTRIDE + k2b + tg];
                ah[mt][2] = As_h[m0 * ASTRIDE + k2b + tg + 4];
                ah[mt][3] = As_h[(m0 + 8) * ASTRIDE + k2b + tg + 4];
                al[mt][0] = As_l[m0 * ASTRIDE + k2b + tg];
                al[mt][1] = As_l[(m0 + 8) * ASTRIDE + k2b + tg];
                al[mt][2] = As_l[m0 * ASTRIDE + k2b + tg + 4];
                al[mt][3] = As_l[(m0 + 8) * ASTRIDE + k2b + tg + 4];
            }
            #pragma unroll
            for (int nt = 0; nt < NT; nt++) {
                int n0 = nW + nt * 8 + gid;
                bh[nt][0] = Bs_h[(k2b + tg) * BSTRIDE + n0];
                bh[nt][1] = Bs_h[(k2b + tg + 4) * BSTRIDE + n0];
                bl[nt][0] = Bs_l[(k2b + tg) * BSTRIDE + n0];
                bl[nt][1] = Bs_l[(k2b + tg + 4) * BSTRIDE + n0];
            }
            #pragma unroll
            for (int mt = 0; mt < MT; mt++)
                #pragma unroll
                for (int nt = 0; nt < NT; nt++) {
                    mma_bf16(acc[mt][nt], ah[mt], bh[nt]);
                    mma_bf16(acc[mt][nt], ah[mt], bl[nt]);
                    mma_bf16(acc[mt][nt], al[mt], bh[nt]);
                }
        }
        stage ^= 1;
    }

    const int N2 = N >> 1;
    #pragma unroll
    for (int mt = 0; mt < MT; mt++) {
        size_t row0 = bm + mW + mt * 16 + gid;
        size_t row1 = row0 + 8;
        #pragma unroll
        for (int nt = 0; nt < NT; nt++) {
            int col = (int)bn + nW + nt * 8 + 2 * tg;
            float b0 = 0.f, b1 = 0.f;
            if (BIAS) { b0 = bias[col]; b1 = bias[col + 1]; }
            float v00 = acc[mt][nt][0] + b0, v01 = acc[mt][nt][1] + b1;
            float v10 = acc[mt][nt][2] + b0, v11 = acc[mt][nt][3] + b1;
            if (ACT == 1) {
                v00 = v00 / (1.f + expf(-v00));
                v01 = v01 / (1.f + expf(-v01));
                v10 = v10 / (1.f + expf(-v10));
                v11 = v11 / (1.f + expf(-v11));
            }
            if (OUT == 0) {
                *(float2*)(Cf + row0 * N + col) = make_float2(v00, v01);
                *(float2*)(Cf + row1 * N + col) = make_float2(v10, v11);
            } else {
                int hc = (col >> 1);
                uint32_t h, l;
                split_pack(v00, v01, h, l);
                Chi[row0 * N2 + hc] = h; Clo[row0 * N2 + hc] = l;
                split_pack(v10, v11, h, l);
                Chi[row1 * N2 + hc] = h; Clo[row1 * N2 + hc] = l;
            }
        }
    }
}

// ---------------- gate + fusion LN v4: 2 rows/warp iteration ----------------
__global__ __launch_bounds__(256) void gate_fuse_v4(
    const float* __restrict__ sem, const float* __restrict__ col,
    const float* __restrict__ w1, const float* __restrict__ b1,
    const float* __restrict__ lng, const float* __restrict__ lnb,
    const float* __restrict__ w2, const float* __restrict__ b2,
    const float* __restrict__ flg, const float* __restrict__ flb,
    float* __restrict__ gate_out, float* __restrict__ fh, float* __restrict__ fl)
{
    extern __shared__ float sm[];
    float* w1s  = sm;
    float* w2s  = w1s + 64 * 128;
    float* b1s  = w2s + 128 * 64;
    float* lngs = b1s + 128;
    float* lnbs = lngs + 128;
    float* b2s  = lnbs + 128;
    float* flgs = b2s + 64;
    float* flbs = flgs + 832;

    const int tid  = threadIdx.x;
    const int lane = tid & 31;
    const int wid  = tid >> 5;

    for (int i = tid; i < 64 * 128; i += 256) w1s[i] = w1[i];
    for (int i = tid; i < 128 * 64; i += 256) w2s[i] = w2[i];
    if (tid < 128) { b1s[tid] = b1[tid]; lngs[tid] = lng[tid]; lnbs[tid] = lnb[tid]; }
    if (tid < 64)  b2s[tid] = b2[tid];
    for (int i = tid; i < 832; i += 256) { flgs[i] = flg[i]; flbs[i] = flb[i]; }
    __syncthreads();

    const int gwarp  = blockIdx.x * 8 + wid;
    const int nwarps = gridDim.x * 8;

    for (int base = 2 * gwarp; base < BATCH; base += 2 * nwarps) {
        const int rX = base, rY = base + 1;
        const float cX0 = col[(size_t)rX * 64 + lane];
        const float cX1 = col[(size_t)rX * 64 + 32 + lane];
        const float cY0 = col[(size_t)rY * 64 + lane];
        const float cY1 = col[(size_t)rY * 64 + 32 + lane];

        float hX[4], hY[4];
        #pragma unroll
        for (int t = 0; t < 4; t++) { hX[t] = b1s[lane + 32 * t]; hY[t] = hX[t]; }
        #pragma unroll
        for (int d = 0; d < 64; d++) {
            float vX = (d < 32) ? __shfl_sync(0xffffffffu, cX0, d)
                                : __shfl_sync(0xffffffffu, cX1, d - 32);
            float vY = (d < 32) ? __shfl_sync(0xffffffffu, cY0, d)
                                : __shfl_sync(0xffffffffu, cY1, d - 32);
            #pragma unroll
            for (int t = 0; t < 4; t++) {
                float w = w1s[d * 128 + lane + 32 * t];
                hX[t] += vX * w;
                hY[t] += vY * w;
            }
        }

        float sX = hX[0] + hX[1] + hX[2] + hX[3];
        float sY = hY[0] + hY[1] + hY[2] + hY[3];
        #pragma unroll
        for (int o = 16; o > 0; o >>= 1) {
            sX += __shfl_xor_sync(0xffffffffu, sX, o);
            sY += __shfl_xor_sync(0xffffffffu, sY, o);
        }
        float mX = sX * (1.f / 128.f), mY = sY * (1.f / 128.f);
        float vX = 0.f, vY = 0.f;
        #pragma unroll
        for (int t = 0; t < 4; t++) {
            float dX = hX[t] - mX; vX += dX * dX;
            float dY = hY[t] - mY; vY += dY * dY;
        }
        #pragma unroll
        for (int o = 16; o > 0; o >>= 1) {
            vX += __shfl_xor_sync(0xffffffffu, vX, o);
            vY += __shfl_xor_sync(0xffffffffu, vY, o);
        }
        float iX = rsqrtf(vX * (1.f / 128.f) + 1e-5f);
        float iY = rsqrtf(vY * (1.f / 128.f) + 1e-5f);
        #pragma unroll
        for (int t = 0; t < 4; t++) {
            float g = lngs[lane + 32 * t], bb = lnbs[lane + 32 * t];
            hX[t] = fmaxf((hX[t] - mX) * iX * g + bb, 0.f);
            hY[t] = fmaxf((hY[t] - mY) * iY * g + bb, 0.f);
        }

        float gX0 = b2s[lane], gX1 = b2s[lane + 32];
        float gY0 = gX0, gY1 = gX1;
        #pragma unroll
        for (int j = 0; j < 128; j++) {
            float hvX = __shfl_sync(0xffffffffu, hX[j >> 5], j & 31);
            float hvY = __shfl_sync(0xffffffffu, hY[j >> 5], j & 31);
            float wa = w2s[j * 64 + lane];
            float wb = w2s[j * 64 + lane + 32];
            gX0 += hvX * wa; gX1 += hvX * wb;
            gY0 += hvY * wa; gY1 += hvY * wb;
        }
        gX0 = 1.f / (1.f + expf(-gX0));
        gX1 = 1.f / (1.f + expf(-gX1));
        gY0 = 1.f / (1.f + expf(-gY0));
        gY1 = 1.f / (1.f + expf(-gY1));
        gate_out[(size_t)rX * 64 + lane]      = gX0;
        gate_out[(size_t)rX * 64 + 32 + lane] = gX1;
        gate_out[(size_t)rY * 64 + lane]      = gY0;
        gate_out[(size_t)rY * 64 + 32 + lane] = gY1;
        const float dX0 = gX0 * cX0, dX1 = gX1 * cX1;
        const float dY0 = gY0 * cY0, dY1 = gY1 * cY1;

        float svX[24], svY[24];
        const float* spX = sem + (size_t)rX * 768;
        const float* spY = sem + (size_t)rY * 768;
        float sumX = dX0 + dX1, sumY = dY0 + dY1;
        #pragma unroll
        for (int k = 0; k < 24; k++) {
            svX[k] = spX[lane + 32 * k]; sumX += svX[k];
            svY[k] = spY[lane + 32 * k]; sumY += svY[k];
        }
        #pragma unroll
        for (int o = 16; o > 0; o >>= 1) {
            sumX += __shfl_xor_sync(0xffffffffu, sumX, o);
            sumY += __shfl_xor_sync(0xffffffffu, sumY, o);
        }
        mX = sumX * (1.f / 832.f); mY = sumY * (1.f / 832.f);
        float varX = 0.f, varY = 0.f;
        { float d = dX0 - mX; varX += d * d; d = dX1 - mX; varX += d * d; }
        { float d = dY0 - mY; varY += d * d; d = dY1 - mY; varY += d * d; }
        #pragma unroll
        for (int k = 0; k < 24; k++) {
            float dXk = svX[k] - mX; varX += dXk * dXk;
            float dYk = svY[k] - mY; varY += dYk * dYk;
        }
        #pragma unroll
        for (int o = 16; o > 0; o >>= 1) {
            varX += __shfl_xor_sync(0xffffffffu, varX, o);
            varY += __shfl_xor_sync(0xffffffffu, varY, o);
        }
        iX = rsqrtf(varX * (1.f / 832.f) + 1e-5f);
        iY = rsqrtf(varY * (1.f / 832.f) + 1e-5f);

        float* fhX = fh + (size_t)rX * 832;
        float* flX = fl + (size_t)rX * 832;
        float* fhY = fh + (size_t)rY * 832;
        float* flY = fl + (size_t)rY * 832;
        #pragma unroll
        for (int k = 0; k < 24; k++) {
            int i = lane + 32 * k;
            float g = flgs[i], bb = flbs[i];
            float fX = (svX[k] - mX) * iX * g + bb;
            float fY = (svY[k] - mY) * iY * g + bb;
            float hvX = tf32_round(fX), hvY = tf32_round(fY);
            fhX[i] = hvX; flX[i] = fX - hvX;
            fhY[i] = hvY; flY[i] = fY - hvY;
        }
        {
            int i = 768 + lane;
            float g = flgs[i], bb = flbs[i];
            float fX = (dX0 - mX) * iX * g + bb;
            float fY = (dY0 - mY) * iY * g + bb;
            float hvX = tf32_round(fX), hvY = tf32_round(fY);
            fhX[i] = hvX; flX[i] = fX - hvX;
            fhY[i] = hvY; flY[i] = fY - hvY;
            i = 768 + 32 + lane;
            g = flgs[i]; bb = flbs[i];
            fX = (dX1 - mX) * iX * g + bb;
            fY = (dY1 - mY) * iY * g + bb;
            hvX = tf32_round(fX); hvY = tf32_round(fY);
            fhX[i] = hvX; flX[i] = fX - hvX;
            fhY[i] = hvY; flY[i] = fY - hvY;
        }
    }
}

// ---------------- residual quantization: warp-per-row, zero syncs in loop ----------------
__global__ __launch_bounds__(256) void rq_warp_kernel(
    const float* __restrict__ cb,
    float* __restrict__ resid,
    float* __restrict__ zq,
    float* __restrict__ codes,
    uint32_t* __restrict__ zqh, uint32_t* __restrict__ zql,
    int layer)
{
    extern __shared__ float cbs[];  // 256*65
    __shared__ float cbn[256];
    __shared__ float blk[256];

    const int tid  = threadIdx.x;
    const int lane = tid & 31;
    const int wid  = tid >> 5;

    for (int i = tid; i < 256 * 64; i += 256) {
        int c = i >> 6, d = i & 63;
        cbs[c * 65 + d] = cb[i];
    }
    __syncthreads();
    {
        float nv = 0.f;
        #pragma unroll 16
        for (int d = 0; d < 64; d++) { float v = cbs[tid * 65 + d]; nv += v * v; }
        cbn[tid] = 0.5f * nv;
    }
    __syncthreads();

    const int gwarp  = blockIdx.x * 8 + wid;
    const int nwarps = gridDim.x * 8;
    float lossAcc = 0.f;

    for (int base = 2 * gwarp; base < BATCH; base += 2 * nwarps) {
        const int rowA = base, rowB = base + 1;
        float a0 = resid[(size_t)rowA * 64 + lane];
        float a1 = resid[(size_t)rowA * 64 + 32 + lane];
        float b0 = resid[(size_t)rowB * 64 + lane];
        float b1 = resid[(size_t)rowB * 64 + 32 + lane];

        float sa = a0 * a0 + a1 * a1;
        float sb = b0 * b0 + b1 * b1;
        #pragma unroll
        for (int o = 16; o > 0; o >>= 1) {
            sa += __shfl_xor_sync(0xffffffffu, sa, o);
            sb += __shfl_xor_sync(0xffffffffu, sb, o);
        }
        sa = __shfl_sync(0xffffffffu, sa, 0);
        sb = __shfl_sync(0xffffffffu, sb, 0);
        float invA = 1.f / fmaxf(sqrtf(sa), 1e-12f);
        float invB = 1.f / fmaxf(sqrtf(sb), 1e-12f);
        a0 *= invA; a1 *= invA;
        b0 *= invB; b1 *= invB;

        float accA[8], accB[8];
        #pragma unroll
        for (int j = 0; j < 8; j++) {
            float n = cbn[lane + 32 * j];
            accA[j] = -n; accB[j] = -n;
        }
        #pragma unroll 8
        for (int d = 0; d < 64; d++) {
            float ra = (d < 32) ? __shfl_sync(0xffffffffu, a0, d)
                                : __shfl_sync(0xffffffffu, a1, d - 32);
            float rb = (d < 32) ? __shfl_sync(0xffffffffu, b0, d)
                                : __shfl_sync(0xffffffffu, b1, d - 32);
            #pragma unroll
            for (int j = 0; j < 8; j++) {
                float w = cbs[(lane + 32 * j) * 65 + d];
                accA[j] += ra * w;
                accB[j] += rb * w;
            }
        }

        float bvA = accA[0], bvB = accB[0];
        int   bcA = lane,    bcB = lane;
        #pragma unroll
        for (int j = 1; j < 8; j++) {
            int c = lane + 32 * j;
            if (accA[j] > bvA) { bvA = accA[j]; bcA = c; }
            if (accB[j] > bvB) { bvB = accB[j]; bcB = c; }
        }
        #pragma unroll
        for (int o = 16; o > 0; o >>= 1) {
            float ovA = __shfl_xor_sync(0xffffffffu, bvA, o);
            int   ocA = __shfl_xor_sync(0xffffffffu, bcA, o);
            if (ovA > bvA || (ovA == bvA && ocA < bcA)) { bvA = ovA; bcA = ocA; }
            float ovB = __shfl_xor_sync(0xffffffffu, bvB, o);
            int   ocB = __shfl_xor_sync(0xffffffffu, bcB, o);
            if (ovB > bvB || (ovB == bvB && ocB < bcB)) { bvB = ovB; bcB = ocB; }
        }

        float eA0 = cbs[bcA * 65 + lane], eA1 = cbs[bcA * 65 + 32 + lane];
        float eB0 = cbs[bcB * 65 + lane], eB1 = cbs[bcB * 65 + 32 + lane];

        size_t oA = (size_t)rowA * 64 + lane, oB = (size_t)rowB * 64 + lane;
        float zA0, zA1, zB0, zB1;
        if (layer == 0) { zA0 = eA0; zA1 = eA1; zB0 = eB0; zB1 = eB1; }
        else {
            zA0 = zq[oA] + eA0; zA1 = zq[oA + 32] + eA1;
            zB0 = zq[oB] + eB0; zB1 = zq[oB + 32] + eB1;
        }
        zq[oA] = zA0; zq[oA + 32] = zA1;
        zq[oB] = zB0; zq[oB + 32] = zB1;
        resid[oA] = a0 - eA0; resid[oA + 32] = a1 - eA1;
        resid[oB] = b0 - eB0; resid[oB + 32] = b1 - eB1;
        {
            float d;
            d = eA0 - a0; lossAcc += d * d;
            d = eA1 - a1; lossAcc += d * d;
            d = eB0 - b0; lossAcc += d * d;
            d = eB1 - b1; lossAcc += d * d;
        }
        if (lane == 0) {
            codes[(size_t)rowA * 3 + layer] = (float)bcA;
            codes[(size_t)rowB * 3 + layer] = (float)bcB;
        }

        if (layer == 2) {
            const int i0 = (2 * lane) & 31;
            const int i1 = (2 * lane + 1) & 31;
            float s0A = __shfl_sync(0xffffffffu, zA0, i0);
            float s1A = __shfl_sync(0xffffffffu, zA1, i0);
            float t0A = __shfl_sync(0xffffffffu, zA0, i1);
            float t1A = __shfl_sync(0xffffffffu, zA1, i1);
            float s0B = __shfl_sync(0xffffffffu, zB0, i0);
            float s1B = __shfl_sync(0xffffffffu, zB1, i0);
            float t0B = __shfl_sync(0xffffffffu, zB0, i1);
            float t1B = __shfl_sync(0xffffffffu, zB1, i1);
            float zaA = (lane < 16) ? s0A : s1A;
            float zbA = (lane < 16) ? t0A : t1A;
            float zaB = (lane < 16) ? s0B : s1B;
            float zbB = (lane < 16) ? t0B : t1B;
            uint32_t h, l;
            split_pack(zaA, zbA, h, l);
            zqh[(size_t)rowA * 32 + lane] = h; zql[(size_t)rowA * 32 + lane] = l;
            split_pack(zaB, zbB, h, l);
            zqh[(size_t)rowB * 32 + lane] = h; zql[(size_t)rowB * 32 + lane] = l;
        }
    }

    blk[tid] = lossAcc; __syncthreads();
    for (int st = 128; st > 0; st >>= 1) { if (tid < st) blk[tid] += blk[tid + st]; __syncthreads(); }
    if (tid == 0) atomicAdd(&g_loss, (double)blk[0]);
}

// ---------------- row LN + ReLU -> bf16 pairs ----------------
template<int W, int T>
__global__ __launch_bounds__(T) void ln_pair(
    const float* __restrict__ in, const float* __restrict__ g,
    const float* __restrict__ b, uint32_t* __restrict__ oh, uint32_t* __restrict__ ol)
{
    constexpr int J  = W / (2 * T);
    constexpr int NW = T / 32;
    __shared__ float red[NW];
    __shared__ float s_m, s_i;
    const int tid = threadIdx.x, lane = tid & 31, wid = tid >> 5;

    for (int row = blockIdx.x; row < BATCH; row += gridDim.x) {
        const float2* ip = (const float2*)(in + (size_t)row * W);
        float2 x[J];
        float s = 0.f;
        #pragma unroll
        for (int j = 0; j < J; j++) { x[j] = ip[tid + T * j]; s += x[j].x + x[j].y; }
        #pragma unroll
        for (int o = 16; o > 0; o >>= 1) s += __shfl_xor_sync(0xffffffffu, s, o);
        if (lane == 0) red[wid] = s;
        __syncthreads();
        if (tid < 32) {
            float v = (tid < NW) ? red[tid] : 0.f;
            #pragma unroll
            for (int o = NW / 2; o > 0; o >>= 1) v += __shfl_xor_sync(0xffffffffu, v, o);
            if (tid == 0) s_m = v * (1.f / (float)W);
        }
        __syncthreads();
        float m = s_m, v2 = 0.f;
        #pragma unroll
        for (int j = 0; j < J; j++) {
            float d0 = x[j].x - m, d1 = x[j].y - m;
            v2 += d0 * d0 + d1 * d1;
        }
        #pragma unroll
        for (int o = 16; o > 0; o >>= 1) v2 += __shfl_xor_sync(0xffffffffu, v2, o);
        if (lane == 0) red[wid] = v2;
        __syncthreads();
        if (tid < 32) {
            float v = (tid < NW) ? red[tid] : 0.f;
            #pragma unroll
            for (int o = NW / 2; o > 0; o >>= 1) v += __shfl_xor_sync(0xffffffffu, v, o);
            if (tid == 0) s_i = rsqrtf(v * (1.f / (float)W) + 1e-5f);
        }
        __syncthreads();
        float inv = s_i;
        uint32_t* ohp = oh + (size_t)row * (W / 2);
        uint32_t* olp = ol + (size_t)row * (W / 2);
        #pragma unroll
        for (int j = 0; j < J; j++) {
            int p = tid + T * j;
            float2 gg = *(const float2*)(g + 2 * p);
            float2 bb = *(const float2*)(b + 2 * p);
            float v0 = fmaxf((x[j].x - m) * inv * gg.x + bb.x, 0.f);
            float v1 = fmaxf((x[j].y - m) * inv * gg.y + bb.y, 0.f);
            uint32_t h, l;
            split_pack(v0, v1, h, l);
            ohp[p] = h; olp[p] = l;
        }
        __syncthreads();
    }
}

// ---------------- host ----------------
extern "C" void kernel_launch(void* const* d_in, const int* in_sizes, int n_in,
                              void* d_out, int out_size)
{
    (void)in_sizes; (void)n_in; (void)out_size;
    const float* sem_emb  = (const float*)d_in[0];
    const float* col_emb  = (const float*)d_in[1];
    const float* gate_w1  = (const float*)d_in[2];
    const float* gate_b1  = (const float*)d_in[3];
    const float* gate_lng = (const float*)d_in[4];
    const float* gate_lnb = (const float*)d_in[5];
    const float* gate_w2  = (const float*)d_in[6];
    const float* gate_b2  = (const float*)d_in[7];
    const float* fus_lng  = (const float*)d_in[8];
    const float* fus_lnb  = (const float*)d_in[9];
    const float* enc_w1   = (const float*)d_in[10];
    const float* enc_w2   = (const float*)d_in[11];
    const float* enc_w3   = (const float*)d_in[12];
    const float* enc_w4   = (const float*)d_in[13];
    const float* dec_w1   = (const float*)d_in[14];
    const float* dec_w2   = (const float*)d_in[15];
    const float* dec_w3   = (const float*)d_in[16];
    const float* sem_w1   = (const float*)d_in[17];
    const float* sem_b1   = (const float*)d_in[18];
    const float* sem_lng  = (const float*)d_in[19];
    const float* sem_lnb  = (const float*)d_in[20];
    const float* sem_w2   = (const float*)d_in[21];
    const float* sem_b2   = (const float*)d_in[22];
    const float* col_w1   = (const float*)d_in[23];
    const float* col_b1   = (const float*)d_in[24];
    const float* col_lng  = (const float*)d_in[25];
    const float* col_lnb  = (const float*)d_in[26];
    const float* col_w2   = (const float*)d_in[27];
    const float* col_b2   = (const float*)d_in[28];
    const float* codebooks= (const float*)d_in[29];

    float* out = (float*)d_out;
    const size_t B = BATCH;
    float* o_sem   = out;
    float* o_col   = o_sem + B * 768;
    float* o_zq    = o_col + B * 64;
    float* o_codes = o_zq + B * 64;
    float* o_loss  = o_codes + B * 3;
    float* o_gate  = o_loss + 2;

    float *p_res, *p_hh, *p_chh;
    float *p_fh, *p_fl, *p_z1h, *p_z1l, *p_z2h, *p_z2l, *p_z3h, *p_z3l, *p_ewh, *p_ewl;
    cudaGetSymbolAddress((void**)&p_res, g_res);
    cudaGetSymbolAddress((void**)&p_hh,  g_hh);
    cudaGetSymbolAddress((void**)&p_chh, g_chh);
    cudaGetSymbolAddress((void**)&p_fh,  g_fh);  cudaGetSymbolAddress((void**)&p_fl,  g_fl);
    cudaGetSymbolAddress((void**)&p_z1h, g_z1h); cudaGetSymbolAddress((void**)&p_z1l, g_z1l);
    cudaGetSymbolAddress((void**)&p_z2h, g_z2h); cudaGetSymbolAddress((void**)&p_z2l, g_z2l);
    cudaGetSymbolAddress((void**)&p_z3h, g_z3h); cudaGetSymbolAddress((void**)&p_z3l, g_z3l);
    cudaGetSymbolAddress((void**)&p_ewh, g_ewh); cudaGetSymbolAddress((void**)&p_ewl, g_ewl);

    uint32_t *p_zqh, *p_zql, *p_s1h, *p_s1l, *p_s2h, *p_s2l, *p_s3h, *p_s3l;
    uint32_t *p_hlh, *p_hll, *p_chl, *p_cll, *p_whi, *p_wlo;
    cudaGetSymbolAddress((void**)&p_zqh, g_zqh); cudaGetSymbolAddress((void**)&p_zql, g_zql);
    cudaGetSymbolAddress((void**)&p_s1h, g_s1h); cudaGetSymbolAddress((void**)&p_s1l, g_s1l);
    cudaGetSymbolAddress((void**)&p_s2h, g_s2h); cudaGetSymbolAddress((void**)&p_s2l, g_s2l);
    cudaGetSymbolAddress((void**)&p_s3h, g_s3h); cudaGetSymbolAddress((void**)&p_s3l, g_s3l);
    cudaGetSymbolAddress((void**)&p_hlh, g_hlh); cudaGetSymbolAddress((void**)&p_hll, g_hll);
    cudaGetSymbolAddress((void**)&p_chl, g_chl); cudaGetSymbolAddress((void**)&p_cll, g_cll);
    cudaGetSymbolAddress((void**)&p_whi, g_whi); cudaGetSymbolAddress((void**)&p_wlo, g_wlo);

    const int EW1 = 0, EW2 = 425984, EW3 = 557056, EW4 = 589824;
    const int OFF_DEC1 = 0, OFF_DEC2 = 4096, OFF_DEC3 = 20480, OFF_SEM1 = 86016;
    const int OFF_SEM2 = 479232, OFF_COL1 = 1069056, OFF_COL2 = 1134592;

    const int GATE_SMEM  = (64*128 + 128*64 + 128*3 + 64 + 832*2) * 4;
    const int RQ_SMEM    = 256 * 65 * 4;
    const int TF_SMEM_128 = 2 * (2*2560 + 2*16*136) * 4;
    const int TF_SMEM_64  = 2 * (2*2560 + 2*16*72)  * 4;
    const int BF_SMEM_128 = 2 * (2*2560 + 2*16*136) * 4;
    const int BF_SMEM_64  = 2 * (2*2560 + 2*16*72)  * 4;
    cudaFuncSetAttribute(gate_fuse_v4,   cudaFuncAttributeMaxDynamicSharedMemorySize, GATE_SMEM);
    cudaFuncSetAttribute(rq_warp_kernel, cudaFuncAttributeMaxDynamicSharedMemorySize, RQ_SMEM);
    cudaFuncSetAttribute(gemm_tf32_pre<128, 1, 1>, cudaFuncAttributeMaxDynamicSharedMemorySize, TF_SMEM_128);
    cudaFuncSetAttribute(gemm_tf32_pre<64,  0, 0>, cudaFuncAttributeMaxDynamicSharedMemorySize, TF_SMEM_64);
    cudaFuncSetAttribute(gemm_bf16x3<128, 1, false, 1>, cudaFuncAttributeMaxDynamicSharedMemorySize, BF_SMEM_128);
    cudaFuncSetAttribute(gemm_bf16x3<128, 0, true,  0>, cudaFuncAttributeMaxDynamicSharedMemorySize, BF_SMEM_128);
    cudaFuncSetAttribute(gemm_bf16x3<64,  0, true,  0>, cudaFuncAttributeMaxDynamicSharedMemorySize, BF_SMEM_64);

    // launch order: 1 pack_enc, 2 pack_dec, 3 gate, 4 enc1 (ncu target), 5 zero_loss, ...
    pack_enc_tf32<<<512, 256>>>(enc_w1, enc_w2, enc_w3, enc_w4, p_ewh, p_ewl);
    pack_dec_bf16<<<512, 256>>>(dec_w1, dec_w2, dec_w3, sem_w1, sem_w2, col_w1, col_w2,
                                p_whi, p_wlo);

    gate_fuse_v4<<<2048, 256, GATE_SMEM>>>(
        sem_emb, col_emb, gate_w1, gate_b1, gate_lng, gate_lnb,
        gate_w2, gate_b2, fus_lng, fus_lnb, o_gate, p_fh, p_fl);

    gemm_tf32_pre<128, 1, 1><<<dim3(4, 512), 256, TF_SMEM_128>>>(
        p_fh, p_fl, p_ewh + EW1, p_ewl + EW1, nullptr, p_z1h, p_z1l, BATCH, 512, 832);

    zero_loss_kernel<<<1, 1>>>();

    gemm_tf32_pre<128, 1, 1><<<dim3(2, 512), 256, TF_SMEM_128>>>(
        p_z1h, p_z1l, p_ewh + EW2, p_ewl + EW2, nullptr, p_z2h, p_z2l, BATCH, 256, 512);
    gemm_tf32_pre<128, 1, 1><<<dim3(1, 512), 256, TF_SMEM_128>>>(
        p_z2h, p_z2l, p_ewh + EW3, p_ewl + EW3, nullptr, p_z3h, p_z3l, BATCH, 128, 256);
    gemm_tf32_pre<64, 0, 0><<<dim3(1, 512), 256, TF_SMEM_64>>>(
        p_z3h, p_z3l, p_ewh + EW4, p_ewl + EW4, p_res, nullptr, nullptr, BATCH, 64, 128);

    for (int l = 0; l < 3; l++)
        rq_warp_kernel<<<1024, 256, RQ_SMEM>>>(
            codebooks + (size_t)l * 256 * 64, p_res, o_zq, o_codes, p_zqh, p_zql, l);
    finalize_kernel<<<1, 1>>>(o_loss);

    gemm_bf16x3<128, 1, false, 1><<<dim3(1, 512), 256, BF_SMEM_128>>>(
        p_zqh, p_zql, p_whi + OFF_DEC1, p_wlo + OFF_DEC1, nullptr,
        nullptr, p_s1h, p_s1l, BATCH, 128, 64);
    gemm_bf16x3<128, 1, false, 1><<<dim3(2, 512), 256, BF_SMEM_128>>>(
        p_s1h, p_s1l, p_whi + OFF_DEC2, p_wlo + OFF_DEC2, nullptr,
        nullptr, p_s2h, p_s2l, BATCH, 256, 128);
    gemm_bf16x3<128, 1, false, 1><<<dim3(4, 512), 256, BF_SMEM_128>>>(
        p_s2h, p_s2l, p_whi + OFF_DEC3, p_wlo + OFF_DEC3, nullptr,
        nullptr, p_s3h, p_s3l, BATCH, 512, 256);

    gemm_bf16x3<128, 0, true, 0><<<dim3(12, 512), 256, BF_SMEM_128>>>(
        p_s3h, p_s3l, p_whi + OFF_SEM1, p_wlo + OFF_SEM1, sem_b1,
        p_hh, nullptr, nullptr, BATCH, 1536, 512);
    ln_pair<1536, 256><<<8192, 256>>>(p_hh, sem_lng, sem_lnb, p_hlh, p_hll);
    gemm_bf16x3<128, 0, true, 0><<<dim3(6, 512), 256, BF_SMEM_128>>>(
        p_hlh, p_hll, p_whi + OFF_SEM2, p_wlo + OFF_SEM2, sem_b2,
        o_sem, nullptr, nullptr, BATCH, 768, 1536);

    gemm_bf16x3<128, 0, true, 0><<<dim3(2, 512), 256, BF_SMEM_128>>>(
        p_s3h, p_s3l, p_whi + OFF_COL1, p_wlo + OFF_COL1, col_b1,
        p_chh, nullptr, nullptr, BATCH, 256, 512);
    ln_pair<256, 128><<<8192, 128>>>(p_chh, col_lng, col_lnb, p_chl, p_cll);
    gemm_bf16x3<64, 0, true, 0><<<dim3(1, 512), 256, BF_SMEM_64>>>(
        p_chl, p_cll, p_whi + OFF_COL2, p_wlo + OFF_COL2, col_b2,
        o_col, nullptr, nullptr, BATCH, 64, 256);
}

// round 15
// speedup vs baseline: 1.2779x; 1.1597x over previous
#include <cuda_runtime.h>
#include <cuda_bf16.h>
#include <cuda_fp16.h>
#include <math.h>
#include <stdint.h>

#define BATCH 65536

// ---------------- scratch ----------------
__device__ float g_res[(size_t)BATCH * 64];
__device__ float g_hh[(size_t)BATCH * 1536];
__device__ float g_chh[(size_t)BATCH * 256];
__device__ double g_loss;

// fp16 pair activation buffers for encoder (u32 = 2 fp16 along k), values scaled x16
__device__ uint32_t g_fH[(size_t)BATCH * 416], g_fL[(size_t)BATCH * 416];
__device__ uint32_t g_z1H[(size_t)BATCH * 256], g_z1L[(size_t)BATCH * 256];
__device__ uint32_t g_z2H[(size_t)BATCH * 128], g_z2L[(size_t)BATCH * 128];
__device__ uint32_t g_z3H[(size_t)BATCH * 64],  g_z3L[(size_t)BATCH * 64];
// fp16 pair encoder weights ([K/2][N] u32), scaled x16
__device__ uint32_t g_ewh[299008], g_ewl[299008];

// bf16 pair activation buffers (dec/heads): [B][K/2] u32
__device__ uint32_t g_zqh[(size_t)BATCH * 32],  g_zql[(size_t)BATCH * 32];
__device__ uint32_t g_s1h[(size_t)BATCH * 64],  g_s1l[(size_t)BATCH * 64];
__device__ uint32_t g_s2h[(size_t)BATCH * 128], g_s2l[(size_t)BATCH * 128];
__device__ uint32_t g_s3h[(size_t)BATCH * 256], g_s3l[(size_t)BATCH * 256];
__device__ uint32_t g_hlh[(size_t)BATCH * 768], g_hll[(size_t)BATCH * 768];
__device__ uint32_t g_chl[(size_t)BATCH * 128], g_cll[(size_t)BATCH * 128];
// bf16 pair packed dec/head weights ([K][N] k-pair layout)
__device__ uint32_t g_whi[1142784], g_wlo[1142784];

__global__ void zero_loss_kernel() { g_loss = 0.0; }

__global__ void finalize_kernel(float* out_loss) {
    float v = (float)(g_loss / ((double)BATCH * 64.0));
    out_loss[0] = v;
    out_loss[1] = v;
}

// ---------------- helpers ----------------
__device__ __forceinline__ void mma_bf16(float* d, const uint32_t* a, const uint32_t* b) {
    asm volatile(
        "mma.sync.aligned.m16n8k16.row.col.f32.bf16.bf16.f32 "
        "{%0,%1,%2,%3}, {%4,%5,%6,%7}, {%8,%9}, {%0,%1,%2,%3};"
        : "+f"(d[0]), "+f"(d[1]), "+f"(d[2]), "+f"(d[3])
        : "r"(a[0]), "r"(a[1]), "r"(a[2]), "r"(a[3]), "r"(b[0]), "r"(b[1]));
}

__device__ __forceinline__ void mma_f16(float* d, const uint32_t* a, const uint32_t* b) {
    asm volatile(
        "mma.sync.aligned.m16n8k16.row.col.f32.f16.f16.f32 "
        "{%0,%1,%2,%3}, {%4,%5,%6,%7}, {%8,%9}, {%0,%1,%2,%3};"
        : "+f"(d[0]), "+f"(d[1]), "+f"(d[2]), "+f"(d[3])
        : "r"(a[0]), "r"(a[1]), "r"(a[2]), "r"(a[3]), "r"(b[0]), "r"(b[1]));
}

__device__ __forceinline__ void split_pack(float x0, float x1, uint32_t& hi, uint32_t& lo) {
    __nv_bfloat16 h0 = __float2bfloat16_rn(x0);
    __nv_bfloat16 h1 = __float2bfloat16_rn(x1);
    __nv_bfloat16 l0 = __float2bfloat16_rn(x0 - __bfloat162float(h0));
    __nv_bfloat16 l1 = __float2bfloat16_rn(x1 - __bfloat162float(h1));
    hi = ((uint32_t)__bfloat16_as_ushort(h1) << 16) | (uint32_t)__bfloat16_as_ushort(h0);
    lo = ((uint32_t)__bfloat16_as_ushort(l1) << 16) | (uint32_t)__bfloat16_as_ushort(l0);
}

// inputs pre-scaled by 16 by caller
__device__ __forceinline__ void split_pack_h(float x0, float x1, uint32_t& hi, uint32_t& lo) {
    __half h0 = __float2half_rn(x0);
    __half h1 = __float2half_rn(x1);
    __half l0 = __float2half_rn(x0 - __half2float(h0));
    __half l1 = __float2half_rn(x1 - __half2float(h1));
    hi = ((uint32_t)__half_as_ushort(h1) << 16) | (uint32_t)__half_as_ushort(h0);
    lo = ((uint32_t)__half_as_ushort(l1) << 16) | (uint32_t)__half_as_ushort(l0);
}

__device__ __forceinline__ void cp_async16(uint32_t dst, const void* src) {
    asm volatile("cp.async.cg.shared.global [%0], [%1], 16;" :: "r"(dst), "l"(src));
}

__device__ __forceinline__ uint32_t smem_u32(const void* p) {
    uint32_t a;
    asm("{ .reg .u64 t; cvta.to.shared.u64 t, %1; cvt.u32.u64 %0, t; }" : "=r"(a) : "l"(p));
    return a;
}

// ---------------- pack kernels ----------------
// encoder weights -> fp16 pairs ([K/2][N] u32), scaled x16
__global__ void pack_enc_f16(const float* __restrict__ w1, const float* __restrict__ w2,
                             const float* __restrict__ w3, const float* __restrict__ w4,
                             uint32_t* __restrict__ wh, uint32_t* __restrict__ wl)
{
    for (int i = blockIdx.x * blockDim.x + threadIdx.x; i < 299008; i += gridDim.x * blockDim.x) {
        const float* W; int li, N;
        if      (i < 212992) { W = w1; li = i;          N = 512; }
        else if (i < 278528) { W = w2; li = i - 212992; N = 256; }
        else if (i < 294912) { W = w3; li = i - 278528; N = 128; }
        else                 { W = w4; li = i - 294912; N = 64;  }
        int k2 = li / N, n = li - k2 * N;
        float x0 = 16.f * W[(size_t)(2 * k2) * N + n];
        float x1 = 16.f * W[(size_t)(2 * k2 + 1) * N + n];
        uint32_t h, l;
        split_pack_h(x0, x1, h, l);
        wh[i] = h; wl[i] = l;
    }
}

__global__ void pack_dec_bf16(const float* __restrict__ d1, const float* __restrict__ d2,
                              const float* __restrict__ d3, const float* __restrict__ s1,
                              const float* __restrict__ s2, const float* __restrict__ c1,
                              const float* __restrict__ c2,
                              uint32_t* __restrict__ wh, uint32_t* __restrict__ wl)
{
    for (int i = blockIdx.x * blockDim.x + threadIdx.x; i < 1142784; i += gridDim.x * blockDim.x) {
        const float* W; int li, N;
        if      (i < 4096)    { W = d1; li = i;           N = 128;  }
        else if (i < 20480)   { W = d2; li = i - 4096;    N = 256;  }
        else if (i < 86016)   { W = d3; li = i - 20480;   N = 512;  }
        else if (i < 479232)  { W = s1; li = i - 86016;   N = 1536; }
        else if (i < 1069056) { W = s2; li = i - 479232;  N = 768;  }
        else if (i < 1134592) { W = c1; li = i - 1069056; N = 256;  }
        else                  { W = c2; li = i - 1134592; N = 64;   }
        int k2 = li / N, n = li - k2 * N;
        float x0 = W[(size_t)(2 * k2) * N + n];
        float x1 = W[(size_t)(2 * k2 + 1) * N + n];
        uint32_t h, l;
        split_pack(x0, x1, h, l);
        wh[i] = h; wl[i] = l;
    }
}

// ---------------- fp16x3 GEMM (encoder): operands pre-scaled x16, epilogue /256 ----------------
// A: [M][K/2] u32 fp16 pairs (hi,lo). B: [K/2][N] u32 fp16 pairs (hi,lo).
// OUT=0: fp32 Cf (true values). OUT=1: fp16 pair Chi/Clo [M][N/2] scaled x16.
template<int BN, int ACT, int OUT>
__global__ __launch_bounds__(256, 2) void gemm_f16x3(
    const uint32_t* __restrict__ Ahi, const uint32_t* __restrict__ Alo,
    const uint32_t* __restrict__ Bh,  const uint32_t* __restrict__ Bl,
    float* __restrict__ Cf, uint32_t* __restrict__ Chi, uint32_t* __restrict__ Clo,
    int M, int N, int K)
{
    constexpr int ASTRIDE = 20;
    constexpr int A_SZ = 128 * ASTRIDE;
    constexpr int BSTRIDE = BN + 8;
    constexpr int B_SZ = 16 * BSTRIDE;
    constexpr int STAGE = 2 * A_SZ + 2 * B_SZ;
    constexpr int MT = 4;
    constexpr int NT = BN / 32;

    extern __shared__ uint32_t usmem[];
    const uint32_t sbase = smem_u32(usmem);

    const int tid  = threadIdx.x;
    const int warp = tid >> 5;
    const int lane = tid & 31;
    const int gid  = lane >> 2;
    const int tg   = lane & 3;
    const int mW   = (warp & 1) * 64;
    const int nW   = (warp >> 1) * (BN / 4);

    const size_t bm = (size_t)blockIdx.y * 128;
    const size_t bn = (size_t)blockIdx.x * BN;
    const int K2 = K >> 1;
    const uint32_t* Bhb = Bh + bn;
    const uint32_t* Blb = Bl + bn;

    float acc[MT][NT][4];
    #pragma unroll
    for (int i = 0; i < MT; i++)
        #pragma unroll
        for (int j = 0; j < NT; j++)
            #pragma unroll
            for (int r = 0; r < 4; r++) acc[i][j][r] = 0.f;

    const int rowA = tid >> 2;
    const int ccA  = (tid & 3) << 2;

    auto load_stage = [&](int st, int k0) {
        const int k2_0 = k0 >> 1;
        const uint32_t so = (uint32_t)(st * STAGE);
        #pragma unroll
        for (int i = 0; i < 2; i++) {
            int r = rowA + i * 64;
            cp_async16(sbase + (so + r * ASTRIDE + ccA) * 4, Ahi + (bm + r) * (size_t)K2 + k2_0 + ccA);
            cp_async16(sbase + (so + A_SZ + r * ASTRIDE + ccA) * 4, Alo + (bm + r) * (size_t)K2 + k2_0 + ccA);
        }
        #pragma unroll
        for (int i = 0; i < BN / 64; i++) {
            int c  = tid + i * 256;
            int r  = c / (BN / 4);
            int cc = (c % (BN / 4)) << 2;
            cp_async16(sbase + (so + 2 * A_SZ + r * BSTRIDE + cc) * 4, Bhb + (size_t)(k2_0 + r) * N + cc);
            cp_async16(sbase + (so + 2 * A_SZ + B_SZ + r * BSTRIDE + cc) * 4, Blb + (size_t)(k2_0 + r) * N + cc);
        }
        asm volatile("cp.async.commit_group;" ::: "memory");
    };

    load_stage(0, 0);
    int stage = 0;

    for (int k0 = 0; k0 < K; k0 += 32) {
        asm volatile("cp.async.wait_group 0;" ::: "memory");
        __syncthreads();
        const bool more = (k0 + 32) < K;
        if (more) load_stage(stage ^ 1, k0 + 32);

        const uint32_t* As_h = usmem + stage * STAGE;
        const uint32_t* As_l = As_h + A_SZ;
        const uint32_t* Bs_h = As_l + A_SZ;
        const uint32_t* Bs_l = Bs_h + B_SZ;

        #pragma unroll
        for (int s = 0; s < 2; s++) {
            const int k2b = s * 8;
            uint32_t ah[MT][4], al[MT][4], bh[NT][2], bl[NT][2];
            #pragma unroll
            for (int mt = 0; mt < MT; mt++) {
                int m0 = mW + mt * 16 + gid;
                ah[mt][0] = As_h[m0 * ASTRIDE + k2b + tg];
                ah[mt][1] = As_h[(m0 + 8) * ASTRIDE + k2b + tg];
                ah[mt][2] = As_h[m0 * ASTRIDE + k2b + tg + 4];
                ah[mt][3] = As_h[(m0 + 8) * ASTRIDE + k2b + tg + 4];
                al[mt][0] = As_l[m0 * ASTRIDE + k2b + tg];
                al[mt][1] = As_l[(m0 + 8) * ASTRIDE + k2b + tg];
                al[mt][2] = As_l[m0 * ASTRIDE + k2b + tg + 4];
                al[mt][3] = As_l[(m0 + 8) * ASTRIDE + k2b + tg + 4];
            }
            #pragma unroll
            for (int nt = 0; nt < NT; nt++) {
                int n0 = nW + nt * 8 + gid;
                bh[nt][0] = Bs_h[(k2b + tg) * BSTRIDE + n0];
                bh[nt][1] = Bs_h[(k2b + tg + 4) * BSTRIDE + n0];
                bl[nt][0] = Bs_l[(k2b + tg) * BSTRIDE + n0];
                bl[nt][1] = Bs_l[(k2b + tg + 4) * BSTRIDE + n0];
            }
            #pragma unroll
            for (int mt = 0; mt < MT; mt++)
                #pragma unroll
                for (int nt = 0; nt < NT; nt++) {
                    mma_f16(acc[mt][nt], ah[mt], bh[nt]);
                    mma_f16(acc[mt][nt], ah[mt], bl[nt]);
                    mma_f16(acc[mt][nt], al[mt], bh[nt]);
                }
        }
        stage ^= 1;
    }

    const int N2 = N >> 1;
    const float S = 1.f / 256.f;
    #pragma unroll
    for (int mt = 0; mt < MT; mt++) {
        size_t row0 = bm + mW + mt * 16 + gid;
        size_t row1 = row0 + 8;
        #pragma unroll
        for (int nt = 0; nt < NT; nt++) {
            int col = (int)bn + nW + nt * 8 + 2 * tg;
            float v00 = acc[mt][nt][0] * S, v01 = acc[mt][nt][1] * S;
            float v10 = acc[mt][nt][2] * S, v11 = acc[mt][nt][3] * S;
            if (ACT == 1) {
                v00 = v00 / (1.f + expf(-v00));
                v01 = v01 / (1.f + expf(-v01));
                v10 = v10 / (1.f + expf(-v10));
                v11 = v11 / (1.f + expf(-v11));
            }
            if (OUT == 0) {
                *(float2*)(Cf + row0 * N + col) = make_float2(v00, v01);
                *(float2*)(Cf + row1 * N + col) = make_float2(v10, v11);
            } else {
                int hc = (col >> 1);
                uint32_t h, l;
                split_pack_h(16.f * v00, 16.f * v01, h, l);
                Chi[row0 * N2 + hc] = h; Clo[row0 * N2 + hc] = l;
                split_pack_h(16.f * v10, 16.f * v11, h, l);
                Chi[row1 * N2 + hc] = h; Clo[row1 * N2 + hc] = l;
            }
        }
    }
}

// ---------------- bf16x3 GEMM (dec/heads, unchanged from r13) ----------------
template<int BN, int ACT, bool BIAS, int OUT>
__global__ __launch_bounds__(256, 2) void gemm_bf16x3(
    const uint32_t* __restrict__ Ahi, const uint32_t* __restrict__ Alo,
    const uint32_t* __restrict__ Bh,  const uint32_t* __restrict__ Bl,
    const float* __restrict__ bias,
    float* __restrict__ Cf, uint32_t* __restrict__ Chi, uint32_t* __restrict__ Clo,
    int M, int N, int K)
{
    constexpr int ASTRIDE = 20;
    constexpr int A_SZ = 128 * ASTRIDE;
    constexpr int BSTRIDE = BN + 8;
    constexpr int B_SZ = 16 * BSTRIDE;
    constexpr int STAGE = 2 * A_SZ + 2 * B_SZ;
    constexpr int MT = 4;
    constexpr int NT = BN / 32;

    extern __shared__ uint32_t usmem[];
    const uint32_t sbase = smem_u32(usmem);

    const int tid  = threadIdx.x;
    const int warp = tid >> 5;
    const int lane = tid & 31;
    const int gid  = lane >> 2;
    const int tg   = lane & 3;
    const int mW   = (warp & 1) * 64;
    const int nW   = (warp >> 1) * (BN / 4);

    const size_t bm = (size_t)blockIdx.y * 128;
    const size_t bn = (size_t)blockIdx.x * BN;
    const int K2 = K >> 1;
    const uint32_t* Bhb = Bh + bn;
    const uint32_t* Blb = Bl + bn;

    float acc[MT][NT][4];
    #pragma unroll
    for (int i = 0; i < MT; i++)
        #pragma unroll
        for (int j = 0; j < NT; j++)
            #pragma unroll
            for (int r = 0; r < 4; r++) acc[i][j][r] = 0.f;

    const int rowA = tid >> 2;
    const int ccA  = (tid & 3) << 2;

    auto load_stage = [&](int st, int k0) {
        const int k2_0 = k0 >> 1;
        const uint32_t so = (uint32_t)(st * STAGE);
        #pragma unroll
        for (int i = 0; i < 2; i++) {
            int r = rowA + i * 64;
            cp_async16(sbase + (so + r * ASTRIDE + ccA) * 4, Ahi + (bm + r) * (size_t)K2 + k2_0 + ccA);
            cp_async16(sbase + (so + A_SZ + r * ASTRIDE + ccA) * 4, Alo + (bm + r) * (size_t)K2 + k2_0 + ccA);
        }
        #pragma unroll
        for (int i = 0; i < BN / 64; i++) {
            int c  = tid + i * 256;
            int r  = c / (BN / 4);
            int cc = (c % (BN / 4)) << 2;
            cp_async16(sbase + (so + 2 * A_SZ + r * BSTRIDE + cc) * 4, Bhb + (size_t)(k2_0 + r) * N + cc);
            cp_async16(sbase + (so + 2 * A_SZ + B_SZ + r * BSTRIDE + cc) * 4, Blb + (size_t)(k2_0 + r) * N + cc);
        }
        asm volatile("cp.async.commit_group;" ::: "memory");
    };

    load_stage(0, 0);
    int stage = 0;

    for (int k0 = 0; k0 < K; k0 += 32) {
        asm volatile("cp.async.wait_group 0;" ::: "memory");
        __syncthreads();
        const bool more = (k0 + 32) < K;
        if (more) load_stage(stage ^ 1, k0 + 32);

        const uint32_t* As_h = usmem + stage * STAGE;
        const uint32_t* As_l = As_h + A_SZ;
        const uint32_t* Bs_h = As_l + A_SZ;
        const uint32_t* Bs_l = Bs_h + B_SZ;

        #pragma unroll
        for (int s = 0; s < 2; s++) {
            const int k2b = s * 8;
            uint32_t ah[MT][4], al[MT][4], bh[NT][2], bl[NT][2];
            #pragma unroll
            for (int mt = 0; mt < MT; mt++) {
                int m0 = mW + mt * 16 + gid;
                ah[mt][0] = As_h[m0 * ASTRIDE + k2b + tg];
                ah[mt][1] = As_h[(m0 + 8) * ASTRIDE + k2b + tg];
                ah[mt][2] = As_h[m0 * ASTRIDE + k2b + tg + 4];
                ah[mt][3] = As_h[(m0 + 8) * ASTRIDE + k2b + tg + 4];
                al[mt][0] = As_l[m0 * ASTRIDE + k2b + tg];
                al[mt][1] = As_l[(m0 + 8) * ASTRIDE + k2b + tg];
                al[mt][2] = As_l[m0 * ASTRIDE + k2b + tg + 4];
                al[mt][3] = As_l[(m0 + 8) * ASTRIDE + k2b + tg + 4];
            }
            #pragma unroll
            for (int nt = 0; nt < NT; nt++) {
                int n0 = nW + nt * 8 + gid;
                bh[nt][0] = Bs_h[(k2b + tg) * BSTRIDE + n0];
                bh[nt][1] = Bs_h[(k2b + tg + 4) * BSTRIDE + n0];
                bl[nt][0] = Bs_l[(k2b + tg) * BSTRIDE + n0];
                bl[nt][1] = Bs_l[(k2b + tg + 4) * BSTRIDE + n0];
            }
            #pragma unroll
            for (int mt = 0; mt < MT; mt++)
                #pragma unroll
                for (int nt = 0; nt < NT; nt++) {
                    mma_bf16(acc[mt][nt], ah[mt], bh[nt]);
                    mma_bf16(acc[mt][nt], ah[mt], bl[nt]);
                    mma_bf16(acc[mt][nt], al[mt], bh[nt]);
                }
        }
        stage ^= 1;
    }

    const int N2 = N >> 1;
    #pragma unroll
    for (int mt = 0; mt < MT; mt++) {
        size_t row0 = bm + mW + mt * 16 + gid;
        size_t row1 = row0 + 8;
        #pragma unroll
        for (int nt = 0; nt < NT; nt++) {
            int col = (int)bn + nW + nt * 8 + 2 * tg;
            float b0 = 0.f, b1 = 0.f;
            if (BIAS) { b0 = bias[col]; b1 = bias[col + 1]; }
            float v00 = acc[mt][nt][0] + b0, v01 = acc[mt][nt][1] + b1;
            float v10 = acc[mt][nt][2] + b0, v11 = acc[mt][nt][3] + b1;
            if (ACT == 1) {
                v00 = v00 / (1.f + expf(-v00));
                v01 = v01 / (1.f + expf(-v01));
                v10 = v10 / (1.f + expf(-v10));
                v11 = v11 / (1.f + expf(-v11));
            }
            if (OUT == 0) {
                *(float2*)(Cf + row0 * N + col) = make_float2(v00, v01);
                *(float2*)(Cf + row1 * N + col) = make_float2(v10, v11);
            } else {
                int hc = (col >> 1);
                uint32_t h, l;
                split_pack(v00, v01, h, l);
                Chi[row0 * N2 + hc] = h; Clo[row0 * N2 + hc] = l;
                split_pack(v10, v11, h, l);
                Chi[row1 * N2 + hc] = h; Clo[row1 * N2 + hc] = l;
            }
        }
    }
}

// ---------------- gate + fusion LN v5: 2 rows/warp, writes fp16x16 pairs ----------------
__global__ __launch_bounds__(256) void gate_fuse_v5(
    const float* __restrict__ sem, const float* __restrict__ col,
    const float* __restrict__ w1, const float* __restrict__ b1,
    const float* __restrict__ lng, const float* __restrict__ lnb,
    const float* __restrict__ w2, const float* __restrict__ b2,
    const float* __restrict__ flg, const float* __restrict__ flb,
    float* __restrict__ gate_out, uint32_t* __restrict__ fH, uint32_t* __restrict__ fL)
{
    extern __shared__ float sm[];
    float* w1s  = sm;
    float* w2s  = w1s + 64 * 128;
    float* b1s  = w2s + 128 * 64;
    float* lngs = b1s + 128;
    float* lnbs = lngs + 128;
    float* b2s  = lnbs + 128;
    float* flgs = b2s + 64;
    float* flbs = flgs + 832;

    const int tid  = threadIdx.x;
    const int lane = tid & 31;
    const int wid  = tid >> 5;

    for (int i = tid; i < 64 * 128; i += 256) w1s[i] = w1[i];
    for (int i = tid; i < 128 * 64; i += 256) w2s[i] = w2[i];
    if (tid < 128) { b1s[tid] = b1[tid]; lngs[tid] = lng[tid]; lnbs[tid] = lnb[tid]; }
    if (tid < 64)  b2s[tid] = b2[tid];
    for (int i = tid; i < 832; i += 256) { flgs[i] = flg[i]; flbs[i] = flb[i]; }
    __syncthreads();

    const int gwarp  = blockIdx.x * 8 + wid;
    const int nwarps = gridDim.x * 8;

    for (int base = 2 * gwarp; base < BATCH; base += 2 * nwarps) {
        const int rX = base, rY = base + 1;
        const float cX0 = col[(size_t)rX * 64 + lane];
        const float cX1 = col[(size_t)rX * 64 + 32 + lane];
        const float cY0 = col[(size_t)rY * 64 + lane];
        const float cY1 = col[(size_t)rY * 64 + 32 + lane];

        float hX[4], hY[4];
        #pragma unroll
        for (int t = 0; t < 4; t++) { hX[t] = b1s[lane + 32 * t]; hY[t] = hX[t]; }
        #pragma unroll
        for (int d = 0; d < 64; d++) {
            float vX = (d < 32) ? __shfl_sync(0xffffffffu, cX0, d)
                                : __shfl_sync(0xffffffffu, cX1, d - 32);
            float vY = (d < 32) ? __shfl_sync(0xffffffffu, cY0, d)
                                : __shfl_sync(0xffffffffu, cY1, d - 32);
            #pragma unroll
            for (int t = 0; t < 4; t++) {
                float w = w1s[d * 128 + lane + 32 * t];
                hX[t] += vX * w;
                hY[t] += vY * w;
            }
        }

        float sX = hX[0] + hX[1] + hX[2] + hX[3];
        float sY = hY[0] + hY[1] + hY[2] + hY[3];
        #pragma unroll
        for (int o = 16; o > 0; o >>= 1) {
            sX += __shfl_xor_sync(0xffffffffu, sX, o);
            sY += __shfl_xor_sync(0xffffffffu, sY, o);
        }
        float mX = sX * (1.f / 128.f), mY = sY * (1.f / 128.f);
        float vX = 0.f, vY = 0.f;
        #pragma unroll
        for (int t = 0; t < 4; t++) {
            float dX = hX[t] - mX; vX += dX * dX;
            float dY = hY[t] - mY; vY += dY * dY;
        }
        #pragma unroll
        for (int o = 16; o > 0; o >>= 1) {
            vX += __shfl_xor_sync(0xffffffffu, vX, o);
            vY += __shfl_xor_sync(0xffffffffu, vY, o);
        }
        float iX = rsqrtf(vX * (1.f / 128.f) + 1e-5f);
        float iY = rsqrtf(vY * (1.f / 128.f) + 1e-5f);
        #pragma unroll
        for (int t = 0; t < 4; t++) {
            float g = lngs[lane + 32 * t], bb = lnbs[lane + 32 * t];
            hX[t] = fmaxf((hX[t] - mX) * iX * g + bb, 0.f);
            hY[t] = fmaxf((hY[t] - mY) * iY * g + bb, 0.f);
        }

        float gX0 = b2s[lane], gX1 = b2s[lane + 32];
        float gY0 = gX0, gY1 = gX1;
        #pragma unroll
        for (int j = 0; j < 128; j++) {
            float hvX = __shfl_sync(0xffffffffu, hX[j >> 5], j & 31);
            float hvY = __shfl_sync(0xffffffffu, hY[j >> 5], j & 31);
            float wa = w2s[j * 64 + lane];
            float wb = w2s[j * 64 + lane + 32];
            gX0 += hvX * wa; gX1 += hvX * wb;
            gY0 += hvY * wa; gY1 += hvY * wb;
        }
        gX0 = 1.f / (1.f + expf(-gX0));
        gX1 = 1.f / (1.f + expf(-gX1));
        gY0 = 1.f / (1.f + expf(-gY0));
        gY1 = 1.f / (1.f + expf(-gY1));
        gate_out[(size_t)rX * 64 + lane]      = gX0;
        gate_out[(size_t)rX * 64 + 32 + lane] = gX1;
        gate_out[(size_t)rY * 64 + lane]      = gY0;
        gate_out[(size_t)rY * 64 + 32 + lane] = gY1;
        const float dX0 = gX0 * cX0, dX1 = gX1 * cX1;
        const float dY0 = gY0 * cY0, dY1 = gY1 * cY1;

        // fusion LN: load sem as float2 pairs (p = lane + 32j, j<12)
        float2 svX[12], svY[12];
        const float2* spX = (const float2*)(sem + (size_t)rX * 768);
        const float2* spY = (const float2*)(sem + (size_t)rY * 768);
        float sumX = dX0 + dX1, sumY = dY0 + dY1;
        #pragma unroll
        for (int j = 0; j < 12; j++) {
            svX[j] = spX[lane + 32 * j]; sumX += svX[j].x + svX[j].y;
            svY[j] = spY[lane + 32 * j]; sumY += svY[j].x + svY[j].y;
        }
        #pragma unroll
        for (int o = 16; o > 0; o >>= 1) {
            sumX += __shfl_xor_sync(0xffffffffu, sumX, o);
            sumY += __shfl_xor_sync(0xffffffffu, sumY, o);
        }
        mX = sumX * (1.f / 832.f); mY = sumY * (1.f / 832.f);
        float varX = 0.f, varY = 0.f;
        { float d = dX0 - mX; varX += d * d; d = dX1 - mX; varX += d * d; }
        { float d = dY0 - mY; varY += d * d; d = dY1 - mY; varY += d * d; }
        #pragma unroll
        for (int j = 0; j < 12; j++) {
            float d0 = svX[j].x - mX, d1 = svX[j].y - mX;
            varX += d0 * d0 + d1 * d1;
            d0 = svY[j].x - mY; d1 = svY[j].y - mY;
            varY += d0 * d0 + d1 * d1;
        }
        #pragma unroll
        for (int o = 16; o > 0; o >>= 1) {
            varX += __shfl_xor_sync(0xffffffffu, varX, o);
            varY += __shfl_xor_sync(0xffffffffu, varY, o);
        }
        iX = rsqrtf(varX * (1.f / 832.f) + 1e-5f);
        iY = rsqrtf(varY * (1.f / 832.f) + 1e-5f);

        uint32_t* fHX = fH + (size_t)rX * 416;
        uint32_t* fLX = fL + (size_t)rX * 416;
        uint32_t* fHY = fH + (size_t)rY * 416;
        uint32_t* fLY = fL + (size_t)rY * 416;
        #pragma unroll
        for (int j = 0; j < 12; j++) {
            int p = lane + 32 * j;
            float ga = flgs[2 * p], gb = flgs[2 * p + 1];
            float ba = flbs[2 * p], bb = flbs[2 * p + 1];
            float f0 = (svX[j].x - mX) * iX * ga + ba;
            float f1 = (svX[j].y - mX) * iX * gb + bb;
            uint32_t h, l;
            split_pack_h(16.f * f0, 16.f * f1, h, l);
            fHX[p] = h; fLX[p] = l;
            f0 = (svY[j].x - mY) * iY * ga + ba;
            f1 = (svY[j].y - mY) * iY * gb + bb;
            split_pack_h(16.f * f0, 16.f * f1, h, l);
            fHY[p] = h; fLY[p] = l;
        }
        {
            // dn pairs: p = 384 + lane covers elements 768+2lane, 768+2lane+1
            const int i0 = (2 * lane) & 31;
            const int i1 = (2 * lane + 1) & 31;
            float s0X = __shfl_sync(0xffffffffu, dX0, i0);
            float s1X = __shfl_sync(0xffffffffu, dX1, i0);
            float t0X = __shfl_sync(0xffffffffu, dX0, i1);
            float t1X = __shfl_sync(0xffffffffu, dX1, i1);
            float s0Y = __shfl_sync(0xffffffffu, dY0, i0);
            float s1Y = __shfl_sync(0xffffffffu, dY1, i0);
            float t0Y = __shfl_sync(0xffffffffu, dY0, i1);
            float t1Y = __shfl_sync(0xffffffffu, dY1, i1);
            float e0X = (lane < 16) ? s0X : s1X;
            float e1X = (lane < 16) ? t0X : t1X;
            float e0Y = (lane < 16) ? s0Y : s1Y;
            float e1Y = (lane < 16) ? t0Y : t1Y;
            int i = 768 + 2 * lane;
            float ga = flgs[i], gb = flgs[i + 1];
            float ba = flbs[i], bb = flbs[i + 1];
            float f0 = (e0X - mX) * iX * ga + ba;
            float f1 = (e1X - mX) * iX * gb + bb;
            uint32_t h, l;
            split_pack_h(16.f * f0, 16.f * f1, h, l);
            fHX[384 + lane] = h; fLX[384 + lane] = l;
            f0 = (e0Y - mY) * iY * ga + ba;
            f1 = (e1Y - mY) * iY * gb + bb;
            split_pack_h(16.f * f0, 16.f * f1, h, l);
            fHY[384 + lane] = h; fLY[384 + lane] = l;
        }
    }
}

// ---------------- residual quantization (unchanged from r13) ----------------
__global__ __launch_bounds__(256) void rq_warp_kernel(
    const float* __restrict__ cb,
    float* __restrict__ resid,
    float* __restrict__ zq,
    float* __restrict__ codes,
    uint32_t* __restrict__ zqh, uint32_t* __restrict__ zql,
    int layer)
{
    extern __shared__ float cbs[];
    __shared__ float cbn[256];
    __shared__ float blk[256];

    const int tid  = threadIdx.x;
    const int lane = tid & 31;
    const int wid  = tid >> 5;

    for (int i = tid; i < 256 * 64; i += 256) {
        int c = i >> 6, d = i & 63;
        cbs[c * 65 + d] = cb[i];
    }
    __syncthreads();
    {
        float nv = 0.f;
        #pragma unroll 16
        for (int d = 0; d < 64; d++) { float v = cbs[tid * 65 + d]; nv += v * v; }
        cbn[tid] = 0.5f * nv;
    }
    __syncthreads();

    const int gwarp  = blockIdx.x * 8 + wid;
    const int nwarps = gridDim.x * 8;
    float lossAcc = 0.f;

    for (int base = 2 * gwarp; base < BATCH; base += 2 * nwarps) {
        const int rowA = base, rowB = base + 1;
        float a0 = resid[(size_t)rowA * 64 + lane];
        float a1 = resid[(size_t)rowA * 64 + 32 + lane];
        float b0 = resid[(size_t)rowB * 64 + lane];
        float b1 = resid[(size_t)rowB * 64 + 32 + lane];

        float sa = a0 * a0 + a1 * a1;
        float sb = b0 * b0 + b1 * b1;
        #pragma unroll
        for (int o = 16; o > 0; o >>= 1) {
            sa += __shfl_xor_sync(0xffffffffu, sa, o);
            sb += __shfl_xor_sync(0xffffffffu, sb, o);
        }
        sa = __shfl_sync(0xffffffffu, sa, 0);
        sb = __shfl_sync(0xffffffffu, sb, 0);
        float invA = 1.f / fmaxf(sqrtf(sa), 1e-12f);
        float invB = 1.f / fmaxf(sqrtf(sb), 1e-12f);
        a0 *= invA; a1 *= invA;
        b0 *= invB; b1 *= invB;

        float accA[8], accB[8];
        #pragma unroll
        for (int j = 0; j < 8; j++) {
            float n = cbn[lane + 32 * j];
            accA[j] = -n; accB[j] = -n;
        }
        #pragma unroll 8
        for (int d = 0; d < 64; d++) {
            float ra = (d < 32) ? __shfl_sync(0xffffffffu, a0, d)
                                : __shfl_sync(0xffffffffu, a1, d - 32);
            float rb = (d < 32) ? __shfl_sync(0xffffffffu, b0, d)
                                : __shfl_sync(0xffffffffu, b1, d - 32);
            #pragma unroll
            for (int j = 0; j < 8; j++) {
                float w = cbs[(lane + 32 * j) * 65 + d];
                accA[j] += ra * w;
                accB[j] += rb * w;
            }
        }

        float bvA = accA[0], bvB = accB[0];
        int   bcA = lane,    bcB = lane;
        #pragma unroll
        for (int j = 1; j < 8; j++) {
            int c = lane + 32 * j;
            if (accA[j] > bvA) { bvA = accA[j]; bcA = c; }
            if (accB[j] > bvB) { bvB = accB[j]; bcB = c; }
        }
        #pragma unroll
        for (int o = 16; o > 0; o >>= 1) {
            float ovA = __shfl_xor_sync(0xffffffffu, bvA, o);
            int   ocA = __shfl_xor_sync(0xffffffffu, bcA, o);
            if (ovA > bvA || (ovA == bvA && ocA < bcA)) { bvA = ovA; bcA = ocA; }
            float ovB = __shfl_xor_sync(0xffffffffu, bvB, o);
            int   ocB = __shfl_xor_sync(0xffffffffu, bcB, o);
            if (ovB > bvB || (ovB == bvB && ocB < bcB)) { bvB = ovB; bcB = ocB; }
        }

        float eA0 = cbs[bcA * 65 + lane], eA1 = cbs[bcA * 65 + 32 + lane];
        float eB0 = cbs[bcB * 65 + lane], eB1 = cbs[bcB * 65 + 32 + lane];

        size_t oA = (size_t)rowA * 64 + lane, oB = (size_t)rowB * 64 + lane;
        float zA0, zA1, zB0, zB1;
        if (layer == 0) { zA0 = eA0; zA1 = eA1; zB0 = eB0; zB1 = eB1; }
        else {
            zA0 = zq[oA] + eA0; zA1 = zq[oA + 32] + eA1;
            zB0 = zq[oB] + eB0; zB1 = zq[oB + 32] + eB1;
        }
        zq[oA] = zA0; zq[oA + 32] = zA1;
        zq[oB] = zB0; zq[oB + 32] = zB1;
        resid[oA] = a0 - eA0; resid[oA + 32] = a1 - eA1;
        resid[oB] = b0 - eB0; resid[oB + 32] = b1 - eB1;
        {
            float d;
            d = eA0 - a0; lossAcc += d * d;
            d = eA1 - a1; lossAcc += d * d;
            d = eB0 - b0; lossAcc += d * d;
            d = eB1 - b1; lossAcc += d * d;
        }
        if (lane == 0) {
            codes[(size_t)rowA * 3 + layer] = (float)bcA;
            codes[(size_t)rowB * 3 + layer] = (float)bcB;
        }

        if (layer == 2) {
            const int i0 = (2 * lane) & 31;
            const int i1 = (2 * lane + 1) & 31;
            float s0A = __shfl_sync(0xffffffffu, zA0, i0);
            float s1A = __shfl_sync(0xffffffffu, zA1, i0);
            float t0A = __shfl_sync(0xffffffffu, zA0, i1);
            float t1A = __shfl_sync(0xffffffffu, zA1, i1);
            float s0B = __shfl_sync(0xffffffffu, zB0, i0);
            float s1B = __shfl_sync(0xffffffffu, zB1, i0);
            float t0B = __shfl_sync(0xffffffffu, zB0, i1);
            float t1B = __shfl_sync(0xffffffffu, zB1, i1);
            float zaA = (lane < 16) ? s0A : s1A;
            float zbA = (lane < 16) ? t0A : t1A;
            float zaB = (lane < 16) ? s0B : s1B;
            float zbB = (lane < 16) ? t0B : t1B;
            uint32_t h, l;
            split_pack(zaA, zbA, h, l);
            zqh[(size_t)rowA * 32 + lane] = h; zql[(size_t)rowA * 32 + lane] = l;
            split_pack(zaB, zbB, h, l);
            zqh[(size_t)rowB * 32 + lane] = h; zql[(size_t)rowB * 32 + lane] = l;
        }
    }

    blk[tid] = lossAcc; __syncthreads();
    for (int st = 128; st > 0; st >>= 1) { if (tid < st) blk[tid] += blk[tid + st]; __syncthreads(); }
    if (tid == 0) atomicAdd(&g_loss, (double)blk[0]);
}

// ---------------- row LN + ReLU -> bf16 pairs (unchanged) ----------------
template<int W, int T>
__global__ __launch_bounds__(T) void ln_pair(
    const float* __restrict__ in, const float* __restrict__ g,
    const float* __restrict__ b, uint32_t* __restrict__ oh, uint32_t* __restrict__ ol)
{
    constexpr int J  = W / (2 * T);
    constexpr int NW = T / 32;
    __shared__ float red[NW];
    __shared__ float s_m, s_i;
    const int tid = threadIdx.x, lane = tid & 31, wid = tid >> 5;

    for (int row = blockIdx.x; row < BATCH; row += gridDim.x) {
        const float2* ip = (const float2*)(in + (size_t)row * W);
        float2 x[J];
        float s = 0.f;
        #pragma unroll
        for (int j = 0; j < J; j++) { x[j] = ip[tid + T * j]; s += x[j].x + x[j].y; }
        #pragma unroll
        for (int o = 16; o > 0; o >>= 1) s += __shfl_xor_sync(0xffffffffu, s, o);
        if (lane == 0) red[wid] = s;
        __syncthreads();
        if (tid < 32) {
            float v = (tid < NW) ? red[tid] : 0.f;
            #pragma unroll
            for (int o = NW / 2; o > 0; o >>= 1) v += __shfl_xor_sync(0xffffffffu, v, o);
            if (tid == 0) s_m = v * (1.f / (float)W);
        }
        __syncthreads();
        float m = s_m, v2 = 0.f;
        #pragma unroll
        for (int j = 0; j < J; j++) {
            float d0 = x[j].x - m, d1 = x[j].y - m;
            v2 += d0 * d0 + d1 * d1;
        }
        #pragma unroll
        for (int o = 16; o > 0; o >>= 1) v2 += __shfl_xor_sync(0xffffffffu, v2, o);
        if (lane == 0) red[wid] = v2;
        __syncthreads();
        if (tid < 32) {
            float v = (tid < NW) ? red[tid] : 0.f;
            #pragma unroll
            for (int o = NW / 2; o > 0; o >>= 1) v += __shfl_xor_sync(0xffffffffu, v, o);
            if (tid == 0) s_i = rsqrtf(v * (1.f / (float)W) + 1e-5f);
        }
        __syncthreads();
        float inv = s_i;
        uint32_t* ohp = oh + (size_t)row * (W / 2);
        uint32_t* olp = ol + (size_t)row * (W / 2);
        #pragma unroll
        for (int j = 0; j < J; j++) {
            int p = tid + T * j;
            float2 gg = *(const float2*)(g + 2 * p);
            float2 bb = *(const float2*)(b + 2 * p);
            float v0 = fmaxf((x[j].x - m) * inv * gg.x + bb.x, 0.f);
            float v1 = fmaxf((x[j].y - m) * inv * gg.y + bb.y, 0.f);
            uint32_t h, l;
            split_pack(v0, v1, h, l);
            ohp[p] = h; olp[p] = l;
        }
        __syncthreads();
    }
}

// ---------------- host ----------------
extern "C" void kernel_launch(void* const* d_in, const int* in_sizes, int n_in,
                              void* d_out, int out_size)
{
    (void)in_sizes; (void)n_in; (void)out_size;
    const float* sem_emb  = (const float*)d_in[0];
    const float* col_emb  = (const float*)d_in[1];
    const float* gate_w1  = (const float*)d_in[2];
    const float* gate_b1  = (const float*)d_in[3];
    const float* gate_lng = (const float*)d_in[4];
    const float* gate_lnb = (const float*)d_in[5];
    const float* gate_w2  = (const float*)d_in[6];
    const float* gate_b2  = (const float*)d_in[7];
    const float* fus_lng  = (const float*)d_in[8];
    const float* fus_lnb  = (const float*)d_in[9];
    const float* enc_w1   = (const float*)d_in[10];
    const float* enc_w2   = (const float*)d_in[11];
    const float* enc_w3   = (const float*)d_in[12];
    const float* enc_w4   = (const float*)d_in[13];
    const float* dec_w1   = (const float*)d_in[14];
    const float* dec_w2   = (const float*)d_in[15];
    const float* dec_w3   = (const float*)d_in[16];
    const float* sem_w1   = (const float*)d_in[17];
    const float* sem_b1   = (const float*)d_in[18];
    const float* sem_lng  = (const float*)d_in[19];
    const float* sem_lnb  = (const float*)d_in[20];
    const float* sem_w2   = (const float*)d_in[21];
    const float* sem_b2   = (const float*)d_in[22];
    const float* col_w1   = (const float*)d_in[23];
    const float* col_b1   = (const float*)d_in[24];
    const float* col_lng  = (const float*)d_in[25];
    const float* col_lnb  = (const float*)d_in[26];
    const float* col_w2   = (const float*)d_in[27];
    const float* col_b2   = (const float*)d_in[28];
    const float* codebooks= (const float*)d_in[29];

    float* out = (float*)d_out;
    const size_t B = BATCH;
    float* o_sem   = out;
    float* o_col   = o_sem + B * 768;
    float* o_zq    = o_col + B * 64;
    float* o_codes = o_zq + B * 64;
    float* o_loss  = o_codes + B * 3;
    float* o_gate  = o_loss + 2;

    float *p_res, *p_hh, *p_chh;
    cudaGetSymbolAddress((void**)&p_res, g_res);
    cudaGetSymbolAddress((void**)&p_hh,  g_hh);
    cudaGetSymbolAddress((void**)&p_chh, g_chh);

    uint32_t *p_fH, *p_fL, *p_z1H, *p_z1L, *p_z2H, *p_z2L, *p_z3H, *p_z3L, *p_ewh, *p_ewl;
    cudaGetSymbolAddress((void**)&p_fH,  g_fH);  cudaGetSymbolAddress((void**)&p_fL,  g_fL);
    cudaGetSymbolAddress((void**)&p_z1H, g_z1H); cudaGetSymbolAddress((void**)&p_z1L, g_z1L);
    cudaGetSymbolAddress((void**)&p_z2H, g_z2H); cudaGetSymbolAddress((void**)&p_z2L, g_z2L);
    cudaGetSymbolAddress((void**)&p_z3H, g_z3H); cudaGetSymbolAddress((void**)&p_z3L, g_z3L);
    cudaGetSymbolAddress((void**)&p_ewh, g_ewh); cudaGetSymbolAddress((void**)&p_ewl, g_ewl);

    uint32_t *p_zqh, *p_zql, *p_s1h, *p_s1l, *p_s2h, *p_s2l, *p_s3h, *p_s3l;
    uint32_t *p_hlh, *p_hll, *p_chl, *p_cll, *p_whi, *p_wlo;
    cudaGetSymbolAddress((void**)&p_zqh, g_zqh); cudaGetSymbolAddress((void**)&p_zql, g_zql);
    cudaGetSymbolAddress((void**)&p_s1h, g_s1h); cudaGetSymbolAddress((void**)&p_s1l, g_s1l);
    cudaGetSymbolAddress((void**)&p_s2h, g_s2h); cudaGetSymbolAddress((void**)&p_s2l, g_s2l);
    cudaGetSymbolAddress((void**)&p_s3h, g_s3h); cudaGetSymbolAddress((void**)&p_s3l, g_s3l);
    cudaGetSymbolAddress((void**)&p_hlh, g_hlh); cudaGetSymbolAddress((void**)&p_hll, g_hll);
    cudaGetSymbolAddress((void**)&p_chl, g_chl); cudaGetSymbolAddress((void**)&p_cll, g_cll);
    cudaGetSymbolAddress((void**)&p_whi, g_whi); cudaGetSymbolAddress((void**)&p_wlo, g_wlo);

    // encoder fp16 weight offsets (u32 pairs): [K/2][N]
    const int EW1 = 0, EW2 = 212992, EW3 = 278528, EW4 = 294912;
    // dec/head packed offsets (u32 pairs)
    const int OFF_DEC1 = 0, OFF_DEC2 = 4096, OFF_DEC3 = 20480, OFF_SEM1 = 86016;
    const int OFF_SEM2 = 479232, OFF_COL1 = 1069056, OFF_COL2 = 1134592;

    const int GATE_SMEM  = (64*128 + 128*64 + 128*3 + 64 + 832*2) * 4;
    const int RQ_SMEM    = 256 * 65 * 4;
    const int GM_SMEM_128 = 2 * (2*2560 + 2*16*136) * 4;   // 75776
    const int GM_SMEM_64  = 2 * (2*2560 + 2*16*72)  * 4;   // 59392
    cudaFuncSetAttribute(gate_fuse_v5,   cudaFuncAttributeMaxDynamicSharedMemorySize, GATE_SMEM);
    cudaFuncSetAttribute(rq_warp_kernel, cudaFuncAttributeMaxDynamicSharedMemorySize, RQ_SMEM);
    cudaFuncSetAttribute(gemm_f16x3<128, 1, 1>, cudaFuncAttributeMaxDynamicSharedMemorySize, GM_SMEM_128);
    cudaFuncSetAttribute(gemm_f16x3<64,  0, 0>, cudaFuncAttributeMaxDynamicSharedMemorySize, GM_SMEM_64);
    cudaFuncSetAttribute(gemm_bf16x3<128, 1, false, 1>, cudaFuncAttributeMaxDynamicSharedMemorySize, GM_SMEM_128);
    cudaFuncSetAttribute(gemm_bf16x3<128, 0, true,  0>, cudaFuncAttributeMaxDynamicSharedMemorySize, GM_SMEM_128);
    cudaFuncSetAttribute(gemm_bf16x3<64,  0, true,  0>, cudaFuncAttributeMaxDynamicSharedMemorySize, GM_SMEM_64);

    // launch order: 1 pack_enc, 2 pack_dec, 3 gate, 4 enc1 (ncu target), 5 zero_loss, ...
    pack_enc_f16<<<512, 256>>>(enc_w1, enc_w2, enc_w3, enc_w4, p_ewh, p_ewl);
    pack_dec_bf16<<<512, 256>>>(dec_w1, dec_w2, dec_w3, sem_w1, sem_w2, col_w1, col_w2,
                                p_whi, p_wlo);

    gate_fuse_v5<<<2048, 256, GATE_SMEM>>>(
        sem_emb, col_emb, gate_w1, gate_b1, gate_lng, gate_lnb,
        gate_w2, gate_b2, fus_lng, fus_lnb, o_gate, p_fH, p_fL);

    // encoder (fp16x3, scaled x16, epilogue /256)
    gemm_f16x3<128, 1, 1><<<dim3(4, 512), 256, GM_SMEM_128>>>(
        p_fH, p_fL, p_ewh + EW1, p_ewl + EW1, nullptr, p_z1H, p_z1L, BATCH, 512, 832);

    zero_loss_kernel<<<1, 1>>>();

    gemm_f16x3<128, 1, 1><<<dim3(2, 512), 256, GM_SMEM_128>>>(
        p_z1H, p_z1L, p_ewh + EW2, p_ewl + EW2, nullptr, p_z2H, p_z2L, BATCH, 256, 512);
    gemm_f16x3<128, 1, 1><<<dim3(1, 512), 256, GM_SMEM_128>>>(
        p_z2H, p_z2L, p_ewh + EW3, p_ewl + EW3, nullptr, p_z3H, p_z3L, BATCH, 128, 256);
    gemm_f16x3<64, 0, 0><<<dim3(1, 512), 256, GM_SMEM_64>>>(
        p_z3H, p_z3L, p_ewh + EW4, p_ewl + EW4, p_res, nullptr, nullptr, BATCH, 64, 128);

    for (int l = 0; l < 3; l++)
        rq_warp_kernel<<<1024, 256, RQ_SMEM>>>(
            codebooks + (size_t)l * 256 * 64, p_res, o_zq, o_codes, p_zqh, p_zql, l);
    finalize_kernel<<<1, 1>>>(o_loss);

    // decoder + heads (bf16x3, unchanged)
    gemm_bf16x3<128, 1, false, 1><<<dim3(1, 512), 256, GM_SMEM_128>>>(
        p_zqh, p_zql, p_whi + OFF_DEC1, p_wlo + OFF_DEC1, nullptr,
        nullptr, p_s1h, p_s1l, BATCH, 128, 64);
    gemm_bf16x3<128, 1, false, 1><<<dim3(2, 512), 256, GM_SMEM_128>>>(
        p_s1h, p_s1l, p_whi + OFF_DEC2, p_wlo + OFF_DEC2, nullptr,
        nullptr, p_s2h, p_s2l, BATCH, 256, 128);
    gemm_bf16x3<128, 1, false, 1><<<dim3(4, 512), 256, GM_SMEM_128>>>(
        p_s2h, p_s2l, p_whi + OFF_DEC3, p_wlo + OFF_DEC3, nullptr,
        nullptr, p_s3h, p_s3l, BATCH, 512, 256);

    gemm_bf16x3<128, 0, true, 0><<<dim3(12, 512), 256, GM_SMEM_128>>>(
        p_s3h, p_s3l, p_whi + OFF_SEM1, p_wlo + OFF_SEM1, sem_b1,
        p_hh, nullptr, nullptr, BATCH, 1536, 512);
    ln_pair<1536, 256><<<8192, 256>>>(p_hh, sem_lng, sem_lnb, p_hlh, p_hll);
    gemm_bf16x3<128, 0, true, 0><<<dim3(6, 512), 256, GM_SMEM_128>>>(
        p_hlh, p_hll, p_whi + OFF_SEM2, p_wlo + OFF_SEM2, sem_b2,
        o_sem, nullptr, nullptr, BATCH, 768, 1536);

    gemm_bf16x3<128, 0, true, 0><<<dim3(2, 512), 256, GM_SMEM_128>>>(
        p_s3h, p_s3l, p_whi + OFF_COL1, p_wlo + OFF_COL1, col_b1,
        p_chh, nullptr, nullptr, BATCH, 256, 512);
    ln_pair<256, 128><<<8192, 128>>>(p_chh, col_lng, col_lnb, p_chl, p_cll);
    gemm_bf16x3<64, 0, true, 0><<<dim3(1, 512), 256, GM_SMEM_64>>>(
        p_chl, p_cll, p_whi + OFF_COL2, p_wlo + OFF_COL2, col_b2,
        o_col, nullptr, nullptr, BATCH, 64, 256);
}

// round 17
// speedup vs baseline: 1.5208x; 1.1901x over previous
#include <cuda_runtime.h>
#include <cuda_bf16.h>
#include <cuda_fp16.h>
#include <math.h>
#include <stdint.h>

#define BATCH 65536

// ---------------- scratch ----------------
__device__ float g_res[(size_t)BATCH * 64];
__device__ float g_hh[(size_t)BATCH * 1536];
__device__ float g_chh[(size_t)BATCH * 256];
__device__ double g_loss;

// fp16 pair activation buffers for encoder (u32 = 2 fp16 along k), values scaled x16
__device__ uint32_t g_fH[(size_t)BATCH * 416], g_fL[(size_t)BATCH * 416];
__device__ uint32_t g_z1H[(size_t)BATCH * 256], g_z1L[(size_t)BATCH * 256];
__device__ uint32_t g_z2H[(size_t)BATCH * 128], g_z2L[(size_t)BATCH * 128];
__device__ uint32_t g_z3H[(size_t)BATCH * 64],  g_z3L[(size_t)BATCH * 64];
// fp16 pair encoder weights ([K/2][N] u32), scaled x16
__device__ uint32_t g_ewh[299008], g_ewl[299008];

// fp16 pair activation buffers (dec/heads), values scaled x16: [B][K/2] u32
__device__ uint32_t g_zqh[(size_t)BATCH * 32],  g_zql[(size_t)BATCH * 32];
__device__ uint32_t g_s1h[(size_t)BATCH * 64],  g_s1l[(size_t)BATCH * 64];
__device__ uint32_t g_s2h[(size_t)BATCH * 128], g_s2l[(size_t)BATCH * 128];
__device__ uint32_t g_s3h[(size_t)BATCH * 256], g_s3l[(size_t)BATCH * 256];
__device__ uint32_t g_hlh[(size_t)BATCH * 768], g_hll[(size_t)BATCH * 768];
__device__ uint32_t g_chl[(size_t)BATCH * 128], g_cll[(size_t)BATCH * 128];
// fp16 pair packed dec/head weights ([K/2][N] k-pair layout), scaled x16
__device__ uint32_t g_whi[1142784], g_wlo[1142784];

__global__ void zero_loss_kernel() { g_loss = 0.0; }

__global__ void finalize_kernel(float* out_loss) {
    float v = (float)(g_loss / ((double)BATCH * 64.0));
    out_loss[0] = v;
    out_loss[1] = v;
}

// ---------------- helpers ----------------
__device__ __forceinline__ void mma_f16(float* d, const uint32_t* a, const uint32_t* b) {
    asm volatile(
        "mma.sync.aligned.m16n8k16.row.col.f32.f16.f16.f32 "
        "{%0,%1,%2,%3}, {%4,%5,%6,%7}, {%8,%9}, {%0,%1,%2,%3};"
        : "+f"(d[0]), "+f"(d[1]), "+f"(d[2]), "+f"(d[3])
        : "r"(a[0]), "r"(a[1]), "r"(a[2]), "r"(a[3]), "r"(b[0]), "r"(b[1]));
}

// inputs pre-scaled by 16 by caller
__device__ __forceinline__ void split_pack_h(float x0, float x1, uint32_t& hi, uint32_t& lo) {
    __half h0 = __float2half_rn(x0);
    __half h1 = __float2half_rn(x1);
    __half l0 = __float2half_rn(x0 - __half2float(h0));
    __half l1 = __float2half_rn(x1 - __half2float(h1));
    hi = ((uint32_t)__half_as_ushort(h1) << 16) | (uint32_t)__half_as_ushort(h0);
    lo = ((uint32_t)__half_as_ushort(l1) << 16) | (uint32_t)__half_as_ushort(l0);
}

__device__ __forceinline__ void cp_async16(uint32_t dst, const void* src) {
    asm volatile("cp.async.cg.shared.global [%0], [%1], 16;" :: "r"(dst), "l"(src));
}

__device__ __forceinline__ uint32_t smem_u32(const void* p) {
    uint32_t a;
    asm("{ .reg .u64 t; cvta.to.shared.u64 t, %1; cvt.u32.u64 %0, t; }" : "=r"(a) : "l"(p));
    return a;
}

// ---------------- pack kernels ----------------
// encoder weights -> fp16 pairs ([K/2][N] u32), scaled x16
__global__ void pack_enc_f16(const float* __restrict__ w1, const float* __restrict__ w2,
                             const float* __restrict__ w3, const float* __restrict__ w4,
                             uint32_t* __restrict__ wh, uint32_t* __restrict__ wl)
{
    for (int i = blockIdx.x * blockDim.x + threadIdx.x; i < 299008; i += gridDim.x * blockDim.x) {
        const float* W; int li, N;
        if      (i < 212992) { W = w1; li = i;          N = 512; }
        else if (i < 278528) { W = w2; li = i - 212992; N = 256; }
        else if (i < 294912) { W = w3; li = i - 278528; N = 128; }
        else                 { W = w4; li = i - 294912; N = 64;  }
        int k2 = li / N, n = li - k2 * N;
        float x0 = 16.f * W[(size_t)(2 * k2) * N + n];
        float x1 = 16.f * W[(size_t)(2 * k2 + 1) * N + n];
        uint32_t h, l;
        split_pack_h(x0, x1, h, l);
        wh[i] = h; wl[i] = l;
    }
}

// dec/head weights -> fp16 pairs ([K/2][N] u32), scaled x16
__global__ void pack_dec_f16(const float* __restrict__ d1, const float* __restrict__ d2,
                             const float* __restrict__ d3, const float* __restrict__ s1,
                             const float* __restrict__ s2, const float* __restrict__ c1,
                             const float* __restrict__ c2,
                             uint32_t* __restrict__ wh, uint32_t* __restrict__ wl)
{
    for (int i = blockIdx.x * blockDim.x + threadIdx.x; i < 1142784; i += gridDim.x * blockDim.x) {
        const float* W; int li, N;
        if      (i < 4096)    { W = d1; li = i;           N = 128;  }
        else if (i < 20480)   { W = d2; li = i - 4096;    N = 256;  }
        else if (i < 86016)   { W = d3; li = i - 20480;   N = 512;  }
        else if (i < 479232)  { W = s1; li = i - 86016;   N = 1536; }
        else if (i < 1069056) { W = s2; li = i - 479232;  N = 768;  }
        else if (i < 1134592) { W = c1; li = i - 1069056; N = 256;  }
        else                  { W = c2; li = i - 1134592; N = 64;   }
        int k2 = li / N, n = li - k2 * N;
        float x0 = 16.f * W[(size_t)(2 * k2) * N + n];
        float x1 = 16.f * W[(size_t)(2 * k2 + 1) * N + n];
        uint32_t h, l;
        split_pack_h(x0, x1, h, l);
        wh[i] = h; wl[i] = l;
    }
}

// ---------------- fp16 split GEMM: operands pre-scaled x16, epilogue /256 ----------------
// A: [M][K/2] u32 fp16 pairs (hi,lo). B: [K/2][N] u32 fp16 pairs (hi,lo).
// TERMS=3: ah*bh + ah*bl + al*bh (full). TERMS=2: ah*bh + al*bh (B hi only; Bl not loaded).
// OUT=0: fp32 Cf (true values, +bias opt). OUT=1: fp16 pair Chi/Clo [M][N/2] scaled x16.
template<int BN, int ACT, bool BIAS, int OUT, int TERMS>
__global__ __launch_bounds__(256, 2) void gemm_f16x(
    const uint32_t* __restrict__ Ahi, const uint32_t* __restrict__ Alo,
    const uint32_t* __restrict__ Bh,  const uint32_t* __restrict__ Bl,
    const float* __restrict__ bias,
    float* __restrict__ Cf, uint32_t* __restrict__ Chi, uint32_t* __restrict__ Clo,
    int M, int N, int K)
{
    constexpr int ASTRIDE = 20;
    constexpr int A_SZ = 128 * ASTRIDE;
    constexpr int BSTRIDE = BN + 8;
    constexpr int B_SZ = 16 * BSTRIDE;
    constexpr int STAGE = 2 * A_SZ + 2 * B_SZ;
    constexpr int MT = 4;
    constexpr int NT = BN / 32;

    extern __shared__ uint32_t usmem[];
    const uint32_t sbase = smem_u32(usmem);

    const int tid  = threadIdx.x;
    const int warp = tid >> 5;
    const int lane = tid & 31;
    const int gid  = lane >> 2;
    const int tg   = lane & 3;
    const int mW   = (warp & 1) * 64;
    const int nW   = (warp >> 1) * (BN / 4);

    const size_t bm = (size_t)blockIdx.y * 128;
    const size_t bn = (size_t)blockIdx.x * BN;
    const int K2 = K >> 1;
    const uint32_t* Bhb = Bh + bn;
    const uint32_t* Blb = Bl + bn;

    float acc[MT][NT][4];
    #pragma unroll
    for (int i = 0; i < MT; i++)
        #pragma unroll
        for (int j = 0; j < NT; j++)
            #pragma unroll
            for (int r = 0; r < 4; r++) acc[i][j][r] = 0.f;

    const int rowA = tid >> 2;
    const int ccA  = (tid & 3) << 2;

    auto load_stage = [&](int st, int k0) {
        const int k2_0 = k0 >> 1;
        const uint32_t so = (uint32_t)(st * STAGE);
        #pragma unroll
        for (int i = 0; i < 2; i++) {
            int r = rowA + i * 64;
            cp_async16(sbase + (so + r * ASTRIDE + ccA) * 4, Ahi + (bm + r) * (size_t)K2 + k2_0 + ccA);
            cp_async16(sbase + (so + A_SZ + r * ASTRIDE + ccA) * 4, Alo + (bm + r) * (size_t)K2 + k2_0 + ccA);
        }
        #pragma unroll
        for (int i = 0; i < BN / 64; i++) {
            int c  = tid + i * 256;
            int r  = c / (BN / 4);
            int cc = (c % (BN / 4)) << 2;
            cp_async16(sbase + (so + 2 * A_SZ + r * BSTRIDE + cc) * 4, Bhb + (size_t)(k2_0 + r) * N + cc);
            if (TERMS == 3)
                cp_async16(sbase + (so + 2 * A_SZ + B_SZ + r * BSTRIDE + cc) * 4, Blb + (size_t)(k2_0 + r) * N + cc);
        }
        asm volatile("cp.async.commit_group;" ::: "memory");
    };

    load_stage(0, 0);
    int stage = 0;

    for (int k0 = 0; k0 < K; k0 += 32) {
        asm volatile("cp.async.wait_group 0;" ::: "memory");
        __syncthreads();
        const bool more = (k0 + 32) < K;
        if (more) load_stage(stage ^ 1, k0 + 32);

        const uint32_t* As_h = usmem + stage * STAGE;
        const uint32_t* As_l = As_h + A_SZ;
        const uint32_t* Bs_h = As_l + A_SZ;
        const uint32_t* Bs_l = Bs_h + B_SZ;

        #pragma unroll
        for (int s = 0; s < 2; s++) {
            const int k2b = s * 8;
            uint32_t ah[MT][4], al[MT][4], bh[NT][2], bl[NT][2];
            #pragma unroll
            for (int mt = 0; mt < MT; mt++) {
                int m0 = mW + mt * 16 + gid;
                ah[mt][0] = As_h[m0 * ASTRIDE + k2b + tg];
                ah[mt][1] = As_h[(m0 + 8) * ASTRIDE + k2b + tg];
                ah[mt][2] = As_h[m0 * ASTRIDE + k2b + tg + 4];
                ah[mt][3] = As_h[(m0 + 8) * ASTRIDE + k2b + tg + 4];
                al[mt][0] = As_l[m0 * ASTRIDE + k2b + tg];
                al[mt][1] = As_l[(m0 + 8) * ASTRIDE + k2b + tg];
                al[mt][2] = As_l[m0 * ASTRIDE + k2b + tg + 4];
                al[mt][3] = As_l[(m0 + 8) * ASTRIDE + k2b + tg + 4];
            }
            #pragma unroll
            for (int nt = 0; nt < NT; nt++) {
                int n0 = nW + nt * 8 + gid;
                bh[nt][0] = Bs_h[(k2b + tg) * BSTRIDE + n0];
                bh[nt][1] = Bs_h[(k2b + tg + 4) * BSTRIDE + n0];
                if (TERMS == 3) {
                    bl[nt][0] = Bs_l[(k2b + tg) * BSTRIDE + n0];
                    bl[nt][1] = Bs_l[(k2b + tg + 4) * BSTRIDE + n0];
                }
            }
            #pragma unroll
            for (int mt = 0; mt < MT; mt++)
                #pragma unroll
                for (int nt = 0; nt < NT; nt++) {
                    mma_f16(acc[mt][nt], ah[mt], bh[nt]);
                    if (TERMS == 3) mma_f16(acc[mt][nt], ah[mt], bl[nt]);
                    mma_f16(acc[mt][nt], al[mt], bh[nt]);
                }
        }
        stage ^= 1;
    }

    const int N2 = N >> 1;
    const float S = 1.f / 256.f;
    #pragma unroll
    for (int mt = 0; mt < MT; mt++) {
        size_t row0 = bm + mW + mt * 16 + gid;
        size_t row1 = row0 + 8;
        #pragma unroll
        for (int nt = 0; nt < NT; nt++) {
            int col = (int)bn + nW + nt * 8 + 2 * tg;
            float b0 = 0.f, b1 = 0.f;
            if (BIAS) { b0 = bias[col]; b1 = bias[col + 1]; }
            float v00 = acc[mt][nt][0] * S + b0, v01 = acc[mt][nt][1] * S + b1;
            float v10 = acc[mt][nt][2] * S + b0, v11 = acc[mt][nt][3] * S + b1;
            if (ACT == 1) {
                v00 = v00 / (1.f + expf(-v00));
                v01 = v01 / (1.f + expf(-v01));
                v10 = v10 / (1.f + expf(-v10));
                v11 = v11 / (1.f + expf(-v11));
            }
            if (OUT == 0) {
                *(float2*)(Cf + row0 * N + col) = make_float2(v00, v01);
                *(float2*)(Cf + row1 * N + col) = make_float2(v10, v11);
            } else {
                int hc = (col >> 1);
                uint32_t h, l;
                split_pack_h(16.f * v00, 16.f * v01, h, l);
                Chi[row0 * N2 + hc] = h; Clo[row0 * N2 + hc] = l;
                split_pack_h(16.f * v10, 16.f * v11, h, l);
                Chi[row1 * N2 + hc] = h; Clo[row1 * N2 + hc] = l;
            }
        }
    }
}

// ---------------- gate + fusion LN v5: 2 rows/warp, writes fp16x16 pairs ----------------
__global__ __launch_bounds__(256) void gate_fuse_v5(
    const float* __restrict__ sem, const float* __restrict__ col,
    const float* __restrict__ w1, const float* __restrict__ b1,
    const float* __restrict__ lng, const float* __restrict__ lnb,
    const float* __restrict__ w2, const float* __restrict__ b2,
    const float* __restrict__ flg, const float* __restrict__ flb,
    float* __restrict__ gate_out, uint32_t* __restrict__ fH, uint32_t* __restrict__ fL)
{
    extern __shared__ float sm[];
    float* w1s  = sm;
    float* w2s  = w1s + 64 * 128;
    float* b1s  = w2s + 128 * 64;
    float* lngs = b1s + 128;
    float* lnbs = lngs + 128;
    float* b2s  = lnbs + 128;
    float* flgs = b2s + 64;
    float* flbs = flgs + 832;

    const int tid  = threadIdx.x;
    const int lane = tid & 31;
    const int wid  = tid >> 5;

    for (int i = tid; i < 64 * 128; i += 256) w1s[i] = w1[i];
    for (int i = tid; i < 128 * 64; i += 256) w2s[i] = w2[i];
    if (tid < 128) { b1s[tid] = b1[tid]; lngs[tid] = lng[tid]; lnbs[tid] = lnb[tid]; }
    if (tid < 64)  b2s[tid] = b2[tid];
    for (int i = tid; i < 832; i += 256) { flgs[i] = flg[i]; flbs[i] = flb[i]; }
    __syncthreads();

    const int gwarp  = blockIdx.x * 8 + wid;
    const int nwarps = gridDim.x * 8;

    for (int base = 2 * gwarp; base < BATCH; base += 2 * nwarps) {
        const int rX = base, rY = base + 1;
        const float cX0 = col[(size_t)rX * 64 + lane];
        const float cX1 = col[(size_t)rX * 64 + 32 + lane];
        const float cY0 = col[(size_t)rY * 64 + lane];
        const float cY1 = col[(size_t)rY * 64 + 32 + lane];

        float hX[4], hY[4];
        #pragma unroll
        for (int t = 0; t < 4; t++) { hX[t] = b1s[lane + 32 * t]; hY[t] = hX[t]; }
        #pragma unroll
        for (int d = 0; d < 64; d++) {
            float vX = (d < 32) ? __shfl_sync(0xffffffffu, cX0, d)
                                : __shfl_sync(0xffffffffu, cX1, d - 32);
            float vY = (d < 32) ? __shfl_sync(0xffffffffu, cY0, d)
                                : __shfl_sync(0xffffffffu, cY1, d - 32);
            #pragma unroll
            for (int t = 0; t < 4; t++) {
                float w = w1s[d * 128 + lane + 32 * t];
                hX[t] += vX * w;
                hY[t] += vY * w;
            }
        }

        float sX = hX[0] + hX[1] + hX[2] + hX[3];
        float sY = hY[0] + hY[1] + hY[2] + hY[3];
        #pragma unroll
        for (int o = 16; o > 0; o >>= 1) {
            sX += __shfl_xor_sync(0xffffffffu, sX, o);
            sY += __shfl_xor_sync(0xffffffffu, sY, o);
        }
        float mX = sX * (1.f / 128.f), mY = sY * (1.f / 128.f);
        float vX = 0.f, vY = 0.f;
        #pragma unroll
        for (int t = 0; t < 4; t++) {
            float dX = hX[t] - mX; vX += dX * dX;
            float dY = hY[t] - mY; vY += dY * dY;
        }
        #pragma unroll
        for (int o = 16; o > 0; o >>= 1) {
            vX += __shfl_xor_sync(0xffffffffu, vX, o);
            vY += __shfl_xor_sync(0xffffffffu, vY, o);
        }
        float iX = rsqrtf(vX * (1.f / 128.f) + 1e-5f);
        float iY = rsqrtf(vY * (1.f / 128.f) + 1e-5f);
        #pragma unroll
        for (int t = 0; t < 4; t++) {
            float g = lngs[lane + 32 * t], bb = lnbs[lane + 32 * t];
            hX[t] = fmaxf((hX[t] - mX) * iX * g + bb, 0.f);
            hY[t] = fmaxf((hY[t] - mY) * iY * g + bb, 0.f);
        }

        float gX0 = b2s[lane], gX1 = b2s[lane + 32];
        float gY0 = gX0, gY1 = gX1;
        #pragma unroll
        for (int j = 0; j < 128; j++) {
            float hvX = __shfl_sync(0xffffffffu, hX[j >> 5], j & 31);
            float hvY = __shfl_sync(0xffffffffu, hY[j >> 5], j & 31);
            float wa = w2s[j * 64 + lane];
            float wb = w2s[j * 64 + lane + 32];
            gX0 += hvX * wa; gX1 += hvX * wb;
            gY0 += hvY * wa; gY1 += hvY * wb;
        }
        gX0 = 1.f / (1.f + expf(-gX0));
        gX1 = 1.f / (1.f + expf(-gX1));
        gY0 = 1.f / (1.f + expf(-gY0));
        gY1 = 1.f / (1.f + expf(-gY1));
        gate_out[(size_t)rX * 64 + lane]      = gX0;
        gate_out[(size_t)rX * 64 + 32 + lane] = gX1;
        gate_out[(size_t)rY * 64 + lane]      = gY0;
        gate_out[(size_t)rY * 64 + 32 + lane] = gY1;
        const float dX0 = gX0 * cX0, dX1 = gX1 * cX1;
        const float dY0 = gY0 * cY0, dY1 = gY1 * cY1;

        float2 svX[12], svY[12];
        const float2* spX = (const float2*)(sem + (size_t)rX * 768);
        const float2* spY = (const float2*)(sem + (size_t)rY * 768);
        float sumX = dX0 + dX1, sumY = dY0 + dY1;
        #pragma unroll
        for (int j = 0; j < 12; j++) {
            svX[j] = spX[lane + 32 * j]; sumX += svX[j].x + svX[j].y;
            svY[j] = spY[lane + 32 * j]; sumY += svY[j].x + svY[j].y;
        }
        #pragma unroll
        for (int o = 16; o > 0; o >>= 1) {
            sumX += __shfl_xor_sync(0xffffffffu, sumX, o);
            sumY += __shfl_xor_sync(0xffffffffu, sumY, o);
        }
        mX = sumX * (1.f / 832.f); mY = sumY * (1.f / 832.f);
        float varX = 0.f, varY = 0.f;
        { float d = dX0 - mX; varX += d * d; d = dX1 - mX; varX += d * d; }
        { float d = dY0 - mY; varY += d * d; d = dY1 - mY; varY += d * d; }
        #pragma unroll
        for (int j = 0; j < 12; j++) {
            float d0 = svX[j].x - mX, d1 = svX[j].y - mX;
            varX += d0 * d0 + d1 * d1;
            d0 = svY[j].x - mY; d1 = svY[j].y - mY;
            varY += d0 * d0 + d1 * d1;
        }
        #pragma unroll
        for (int o = 16; o > 0; o >>= 1) {
            varX += __shfl_xor_sync(0xffffffffu, varX, o);
            varY += __shfl_xor_sync(0xffffffffu, varY, o);
        }
        iX = rsqrtf(varX * (1.f / 832.f) + 1e-5f);
        iY = rsqrtf(varY * (1.f / 832.f) + 1e-5f);

        uint32_t* fHX = fH + (size_t)rX * 416;
        uint32_t* fLX = fL + (size_t)rX * 416;
        uint32_t* fHY = fH + (size_t)rY * 416;
        uint32_t* fLY = fL + (size_t)rY * 416;
        #pragma unroll
        for (int j = 0; j < 12; j++) {
            int p = lane + 32 * j;
            float ga = flgs[2 * p], gb = flgs[2 * p + 1];
            float ba = flbs[2 * p], bb = flbs[2 * p + 1];
            float f0 = (svX[j].x - mX) * iX * ga + ba;
            float f1 = (svX[j].y - mX) * iX * gb + bb;
            uint32_t h, l;
            split_pack_h(16.f * f0, 16.f * f1, h, l);
            fHX[p] = h; fLX[p] = l;
            f0 = (svY[j].x - mY) * iY * ga + ba;
            f1 = (svY[j].y - mY) * iY * gb + bb;
            split_pack_h(16.f * f0, 16.f * f1, h, l);
            fHY[p] = h; fLY[p] = l;
        }
        {
            const int i0 = (2 * lane) & 31;
            const int i1 = (2 * lane + 1) & 31;
            float s0X = __shfl_sync(0xffffffffu, dX0, i0);
            float s1X = __shfl_sync(0xffffffffu, dX1, i0);
            float t0X = __shfl_sync(0xffffffffu, dX0, i1);
            float t1X = __shfl_sync(0xffffffffu, dX1, i1);
            float s0Y = __shfl_sync(0xffffffffu, dY0, i0);
            float s1Y = __shfl_sync(0xffffffffu, dY1, i0);
            float t0Y = __shfl_sync(0xffffffffu, dY0, i1);
            float t1Y = __shfl_sync(0xffffffffu, dY1, i1);
            float e0X = (lane < 16) ? s0X : s1X;
            float e1X = (lane < 16) ? t0X : t1X;
            float e0Y = (lane < 16) ? s0Y : s1Y;
            float e1Y = (lane < 16) ? t0Y : t1Y;
            int i = 768 + 2 * lane;
            float ga = flgs[i], gb = flgs[i + 1];
            float ba = flbs[i], bb = flbs[i + 1];
            float f0 = (e0X - mX) * iX * ga + ba;
            float f1 = (e1X - mX) * iX * gb + bb;
            uint32_t h, l;
            split_pack_h(16.f * f0, 16.f * f1, h, l);
            fHX[384 + lane] = h; fLX[384 + lane] = l;
            f0 = (e0Y - mY) * iY * ga + ba;
            f1 = (e1Y - mY) * iY * gb + bb;
            split_pack_h(16.f * f0, 16.f * f1, h, l);
            fHY[384 + lane] = h; fLY[384 + lane] = l;
        }
    }
}

// ---------------- residual quantization (layer-2 pack -> fp16 x16 pairs) ----------------
__global__ __launch_bounds__(256) void rq_warp_kernel(
    const float* __restrict__ cb,
    float* __restrict__ resid,
    float* __restrict__ zq,
    float* __restrict__ codes,
    uint32_t* __restrict__ zqh, uint32_t* __restrict__ zql,
    int layer)
{
    extern __shared__ float cbs[];
    __shared__ float cbn[256];
    __shared__ float blk[256];

    const int tid  = threadIdx.x;
    const int lane = tid & 31;
    const int wid  = tid >> 5;

    for (int i = tid; i < 256 * 64; i += 256) {
        int c = i >> 6, d = i & 63;
        cbs[c * 65 + d] = cb[i];
    }
    __syncthreads();
    {
        float nv = 0.f;
        #pragma unroll 16
        for (int d = 0; d < 64; d++) { float v = cbs[tid * 65 + d]; nv += v * v; }
        cbn[tid] = 0.5f * nv;
    }
    __syncthreads();

    const int gwarp  = blockIdx.x * 8 + wid;
    const int nwarps = gridDim.x * 8;
    float lossAcc = 0.f;

    for (int base = 2 * gwarp; base < BATCH; base += 2 * nwarps) {
        const int rowA = base, rowB = base + 1;
        float a0 = resid[(size_t)rowA * 64 + lane];
        float a1 = resid[(size_t)rowA * 64 + 32 + lane];
        float b0 = resid[(size_t)rowB * 64 + lane];
        float b1 = resid[(size_t)rowB * 64 + 32 + lane];

        float sa = a0 * a0 + a1 * a1;
        float sb = b0 * b0 + b1 * b1;
        #pragma unroll
        for (int o = 16; o > 0; o >>= 1) {
            sa += __shfl_xor_sync(0xffffffffu, sa, o);
            sb += __shfl_xor_sync(0xffffffffu, sb, o);
        }
        sa = __shfl_sync(0xffffffffu, sa, 0);
        sb = __shfl_sync(0xffffffffu, sb, 0);
        float invA = 1.f / fmaxf(sqrtf(sa), 1e-12f);
        float invB = 1.f / fmaxf(sqrtf(sb), 1e-12f);
        a0 *= invA; a1 *= invA;
        b0 *= invB; b1 *= invB;

        float accA[8], accB[8];
        #pragma unroll
        for (int j = 0; j < 8; j++) {
            float n = cbn[lane + 32 * j];
            accA[j] = -n; accB[j] = -n;
        }
        #pragma unroll 8
        for (int d = 0; d < 64; d++) {
            float ra = (d < 32) ? __shfl_sync(0xffffffffu, a0, d)
                                : __shfl_sync(0xffffffffu, a1, d - 32);
            float rb = (d < 32) ? __shfl_sync(0xffffffffu, b0, d)
                                : __shfl_sync(0xffffffffu, b1, d - 32);
            #pragma unroll
            for (int j = 0; j < 8; j++) {
                float w = cbs[(lane + 32 * j) * 65 + d];
                accA[j] += ra * w;
                accB[j] += rb * w;
            }
        }

        float bvA = accA[0], bvB = accB[0];
        int   bcA = lane,    bcB = lane;
        #pragma unroll
        for (int j = 1; j < 8; j++) {
            int c = lane + 32 * j;
            if (accA[j] > bvA) { bvA = accA[j]; bcA = c; }
            if (accB[j] > bvB) { bvB = accB[j]; bcB = c; }
        }
        #pragma unroll
        for (int o = 16; o > 0; o >>= 1) {
            float ovA = __shfl_xor_sync(0xffffffffu, bvA, o);
            int   ocA = __shfl_xor_sync(0xffffffffu, bcA, o);
            if (ovA > bvA || (ovA == bvA && ocA < bcA)) { bvA = ovA; bcA = ocA; }
            float ovB = __shfl_xor_sync(0xffffffffu, bvB, o);
            int   ocB = __shfl_xor_sync(0xffffffffu, bcB, o);
            if (ovB > bvB || (ovB == bvB && ocB < bcB)) { bvB = ovB; bcB = ocB; }
        }

        float eA0 = cbs[bcA * 65 + lane], eA1 = cbs[bcA * 65 + 32 + lane];
        float eB0 = cbs[bcB * 65 + lane], eB1 = cbs[bcB * 65 + 32 + lane];

        size_t oA = (size_t)rowA * 64 + lane, oB = (size_t)rowB * 64 + lane;
        float zA0, zA1, zB0, zB1;
        if (layer == 0) { zA0 = eA0; zA1 = eA1; zB0 = eB0; zB1 = eB1; }
        else {
            zA0 = zq[oA] + eA0; zA1 = zq[oA + 32] + eA1;
            zB0 = zq[oB] + eB0; zB1 = zq[oB + 32] + eB1;
        }
        zq[oA] = zA0; zq[oA + 32] = zA1;
        zq[oB] = zB0; zq[oB + 32] = zB1;
        resid[oA] = a0 - eA0; resid[oA + 32] = a1 - eA1;
        resid[oB] = b0 - eB0; resid[oB + 32] = b1 - eB1;
        {
            float d;
            d = eA0 - a0; lossAcc += d * d;
            d = eA1 - a1; lossAcc += d * d;
            d = eB0 - b0; lossAcc += d * d;
            d = eB1 - b1; lossAcc += d * d;
        }
        if (lane == 0) {
            codes[(size_t)rowA * 3 + layer] = (float)bcA;
            codes[(size_t)rowB * 3 + layer] = (float)bcB;
        }

        if (layer == 2) {
            const int i0 = (2 * lane) & 31;
            const int i1 = (2 * lane + 1) & 31;
            float s0A = __shfl_sync(0xffffffffu, zA0, i0);
            float s1A = __shfl_sync(0xffffffffu, zA1, i0);
            float t0A = __shfl_sync(0xffffffffu, zA0, i1);
            float t1A = __shfl_sync(0xffffffffu, zA1, i1);
            float s0B = __shfl_sync(0xffffffffu, zB0, i0);
            float s1B = __shfl_sync(0xffffffffu, zB1, i0);
            float t0B = __shfl_sync(0xffffffffu, zB0, i1);
            float t1B = __shfl_sync(0xffffffffu, zB1, i1);
            float zaA = (lane < 16) ? s0A : s1A;
            float zbA = (lane < 16) ? t0A : t1A;
            float zaB = (lane < 16) ? s0B : s1B;
            float zbB = (lane < 16) ? t0B : t1B;
            uint32_t h, l;
            split_pack_h(16.f * zaA, 16.f * zbA, h, l);
            zqh[(size_t)rowA * 32 + lane] = h; zql[(size_t)rowA * 32 + lane] = l;
            split_pack_h(16.f * zaB, 16.f * zbB, h, l);
            zqh[(size_t)rowB * 32 + lane] = h; zql[(size_t)rowB * 32 + lane] = l;
        }
    }

    blk[tid] = lossAcc; __syncthreads();
    for (int st = 128; st > 0; st >>= 1) { if (tid < st) blk[tid] += blk[tid + st]; __syncthreads(); }
    if (tid == 0) atomicAdd(&g_loss, (double)blk[0]);
}

// ---------------- row LN + ReLU -> fp16 x16 pairs ----------------
template<int W, int T>
__global__ __launch_bounds__(T) void ln_pair(
    const float* __restrict__ in, const float* __restrict__ g,
    const float* __restrict__ b, uint32_t* __restrict__ oh, uint32_t* __restrict__ ol)
{
    constexpr int J  = W / (2 * T);
    constexpr int NW = T / 32;
    __shared__ float red[NW];
    __shared__ float s_m, s_i;
    const int tid = threadIdx.x, lane = tid & 31, wid = tid >> 5;

    for (int row = blockIdx.x; row < BATCH; row += gridDim.x) {
        const float2* ip = (const float2*)(in + (size_t)row * W);
        float2 x[J];
        float s = 0.f;
        #pragma unroll
        for (int j = 0; j < J; j++) { x[j] = ip[tid + T * j]; s += x[j].x + x[j].y; }
        #pragma unroll
        for (int o = 16; o > 0; o >>= 1) s += __shfl_xor_sync(0xffffffffu, s, o);
        if (lane == 0) red[wid] = s;
        __syncthreads();
        if (tid < 32) {
            float v = (tid < NW) ? red[tid] : 0.f;
            #pragma unroll
            for (int o = NW / 2; o > 0; o >>= 1) v += __shfl_xor_sync(0xffffffffu, v, o);
            if (tid == 0) s_m = v * (1.f / (float)W);
        }
        __syncthreads();
        float m = s_m, v2 = 0.f;
        #pragma unroll
        for (int j = 0; j < J; j++) {
            float d0 = x[j].x - m, d1 = x[j].y - m;
            v2 += d0 * d0 + d1 * d1;
        }
        #pragma unroll
        for (int o = 16; o > 0; o >>= 1) v2 += __shfl_xor_sync(0xffffffffu, v2, o);
        if (lane == 0) red[wid] = v2;
        __syncthreads();
        if (tid < 32) {
            float v = (tid < NW) ? red[tid] : 0.f;
            #pragma unroll
            for (int o = NW / 2; o > 0; o >>= 1) v += __shfl_xor_sync(0xffffffffu, v, o);
            if (tid == 0) s_i = rsqrtf(v * (1.f / (float)W) + 1e-5f);
        }
        __syncthreads();
        float inv = s_i;
        uint32_t* ohp = oh + (size_t)row * (W / 2);
        uint32_t* olp = ol + (size_t)row * (W / 2);
        #pragma unroll
        for (int j = 0; j < J; j++) {
            int p = tid + T * j;
            float2 gg = *(const float2*)(g + 2 * p);
            float2 bb = *(const float2*)(b + 2 * p);
            float v0 = fmaxf((x[j].x - m) * inv * gg.x + bb.x, 0.f);
            float v1 = fmaxf((x[j].y - m) * inv * gg.y + bb.y, 0.f);
            uint32_t h, l;
            split_pack_h(16.f * v0, 16.f * v1, h, l);
            ohp[p] = h; olp[p] = l;
        }
        __syncthreads();
    }
}

// ---------------- host ----------------
extern "C" void kernel_launch(void* const* d_in, const int* in_sizes, int n_in,
                              void* d_out, int out_size)
{
    (void)in_sizes; (void)n_in; (void)out_size;
    const float* sem_emb  = (const float*)d_in[0];
    const float* col_emb  = (const float*)d_in[1];
    const float* gate_w1  = (const float*)d_in[2];
    const float* gate_b1  = (const float*)d_in[3];
    const float* gate_lng = (const float*)d_in[4];
    const float* gate_lnb = (const float*)d_in[5];
    const float* gate_w2  = (const float*)d_in[6];
    const float* gate_b2  = (const float*)d_in[7];
    const float* fus_lng  = (const float*)d_in[8];
    const float* fus_lnb  = (const float*)d_in[9];
    const float* enc_w1   = (const float*)d_in[10];
    const float* enc_w2   = (const float*)d_in[11];
    const float* enc_w3   = (const float*)d_in[12];
    const float* enc_w4   = (const float*)d_in[13];
    const float* dec_w1   = (const float*)d_in[14];
    const float* dec_w2   = (const float*)d_in[15];
    const float* dec_w3   = (const float*)d_in[16];
    const float* sem_w1   = (const float*)d_in[17];
    const float* sem_b1   = (const float*)d_in[18];
    const float* sem_lng  = (const float*)d_in[19];
    const float* sem_lnb  = (const float*)d_in[20];
    const float* sem_w2   = (const float*)d_in[21];
    const float* sem_b2   = (const float*)d_in[22];
    const float* col_w1   = (const float*)d_in[23];
    const float* col_b1   = (const float*)d_in[24];
    const float* col_lng  = (const float*)d_in[25];
    const float* col_lnb  = (const float*)d_in[26];
    const float* col_w2   = (const float*)d_in[27];
    const float* col_b2   = (const float*)d_in[28];
    const float* codebooks= (const float*)d_in[29];

    float* out = (float*)d_out;
    const size_t B = BATCH;
    float* o_sem   = out;
    float* o_col   = o_sem + B * 768;
    float* o_zq    = o_col + B * 64;
    float* o_codes = o_zq + B * 64;
    float* o_loss  = o_codes + B * 3;
    float* o_gate  = o_loss + 2;

    float *p_res, *p_hh, *p_chh;
    cudaGetSymbolAddress((void**)&p_res, g_res);
    cudaGetSymbolAddress((void**)&p_hh,  g_hh);
    cudaGetSymbolAddress((void**)&p_chh, g_chh);

    uint32_t *p_fH, *p_fL, *p_z1H, *p_z1L, *p_z2H, *p_z2L, *p_z3H, *p_z3L, *p_ewh, *p_ewl;
    cudaGetSymbolAddress((void**)&p_fH,  g_fH);  cudaGetSymbolAddress((void**)&p_fL,  g_fL);
    cudaGetSymbolAddress((void**)&p_z1H, g_z1H); cudaGetSymbolAddress((void**)&p_z1L, g_z1L);
    cudaGetSymbolAddress((void**)&p_z2H, g_z2H); cudaGetSymbolAddress((void**)&p_z2L, g_z2L);
    cudaGetSymbolAddress((void**)&p_z3H, g_z3H); cudaGetSymbolAddress((void**)&p_z3L, g_z3L);
    cudaGetSymbolAddress((void**)&p_ewh, g_ewh); cudaGetSymbolAddress((void**)&p_ewl, g_ewl);

    uint32_t *p_zqh, *p_zql, *p_s1h, *p_s1l, *p_s2h, *p_s2l, *p_s3h, *p_s3l;
    uint32_t *p_hlh, *p_hll, *p_chl, *p_cll, *p_whi, *p_wlo;
    cudaGetSymbolAddress((void**)&p_zqh, g_zqh); cudaGetSymbolAddress((void**)&p_zql, g_zql);
    cudaGetSymbolAddress((void**)&p_s1h, g_s1h); cudaGetSymbolAddress((void**)&p_s1l, g_s1l);
    cudaGetSymbolAddress((void**)&p_s2h, g_s2h); cudaGetSymbolAddress((void**)&p_s2l, g_s2l);
    cudaGetSymbolAddress((void**)&p_s3h, g_s3h); cudaGetSymbolAddress((void**)&p_s3l, g_s3l);
    cudaGetSymbolAddress((void**)&p_hlh, g_hlh); cudaGetSymbolAddress((void**)&p_hll, g_hll);
    cudaGetSymbolAddress((void**)&p_chl, g_chl); cudaGetSymbolAddress((void**)&p_cll, g_cll);
    cudaGetSymbolAddress((void**)&p_whi, g_whi); cudaGetSymbolAddress((void**)&p_wlo, g_wlo);

    // encoder fp16 weight offsets (u32 pairs): [K/2][N]
    const int EW1 = 0, EW2 = 212992, EW3 = 278528, EW4 = 294912;
    // dec/head packed offsets (u32 pairs)
    const int OFF_DEC1 = 0, OFF_DEC2 = 4096, OFF_DEC3 = 20480, OFF_SEM1 = 86016;
    const int OFF_SEM2 = 479232, OFF_COL1 = 1069056, OFF_COL2 = 1134592;

    const int GATE_SMEM  = (64*128 + 128*64 + 128*3 + 64 + 832*2) * 4;
    const int RQ_SMEM    = 256 * 65 * 4;
    const int GM_SMEM_128 = 2 * (2*2560 + 2*16*136) * 4;   // 75776
    const int GM_SMEM_64  = 2 * (2*2560 + 2*16*72)  * 4;   // 59392
    cudaFuncSetAttribute(gate_fuse_v5,   cudaFuncAttributeMaxDynamicSharedMemorySize, GATE_SMEM);
    cudaFuncSetAttribute(rq_warp_kernel, cudaFuncAttributeMaxDynamicSharedMemorySize, RQ_SMEM);
    cudaFuncSetAttribute(gemm_f16x<128, 1, false, 1, 3>, cudaFuncAttributeMaxDynamicSharedMemorySize, GM_SMEM_128);
    cudaFuncSetAttribute(gemm_f16x<64,  0, false, 0, 3>, cudaFuncAttributeMaxDynamicSharedMemorySize, GM_SMEM_64);
    cudaFuncSetAttribute(gemm_f16x<128, 0, true,  0, 2>, cudaFuncAttributeMaxDynamicSharedMemorySize, GM_SMEM_128);
    cudaFuncSetAttribute(gemm_f16x<64,  0, true,  0, 3>, cudaFuncAttributeMaxDynamicSharedMemorySize, GM_SMEM_64);

    // launch order: 1 pack_enc, 2 pack_dec, 3 gate, 4 enc1 (ncu target), 5 zero_loss, ...
    pack_enc_f16<<<512, 256>>>(enc_w1, enc_w2, enc_w3, enc_w4, p_ewh, p_ewl);
    pack_dec_f16<<<512, 256>>>(dec_w1, dec_w2, dec_w3, sem_w1, sem_w2, col_w1, col_w2,
                               p_whi, p_wlo);

    gate_fuse_v5<<<2048, 256, GATE_SMEM>>>(
        sem_emb, col_emb, gate_w1, gate_b1, gate_lng, gate_lnb,
        gate_w2, gate_b2, fus_lng, fus_lnb, o_gate, p_fH, p_fL);

    // encoder (fp16x3, scaled x16)
    gemm_f16x<128, 1, false, 1, 3><<<dim3(4, 512), 256, GM_SMEM_128>>>(
        p_fH, p_fL, p_ewh + EW1, p_ewl + EW1, nullptr, nullptr, p_z1H, p_z1L, BATCH, 512, 832);

    zero_loss_kernel<<<1, 1>>>();

    gemm_f16x<128, 1, false, 1, 3><<<dim3(2, 512), 256, GM_SMEM_128>>>(
        p_z1H, p_z1L, p_ewh + EW2, p_ewl + EW2, nullptr, nullptr, p_z2H, p_z2L, BATCH, 256, 512);
    gemm_f16x<128, 1, false, 1, 3><<<dim3(1, 512), 256, GM_SMEM_128>>>(
        p_z2H, p_z2L, p_ewh + EW3, p_ewl + EW3, nullptr, nullptr, p_z3H, p_z3L, BATCH, 128, 256);
    gemm_f16x<64, 0, false, 0, 3><<<dim3(1, 512), 256, GM_SMEM_64>>>(
        p_z3H, p_z3L, p_ewh + EW4, p_ewl + EW4, nullptr, p_res, nullptr, nullptr, BATCH, 64, 128);

    for (int l = 0; l < 3; l++)
        rq_warp_kernel<<<1024, 256, RQ_SMEM>>>(
            codebooks + (size_t)l * 256 * 64, p_res, o_zq, o_codes, p_zqh, p_zql, l);
    finalize_kernel<<<1, 1>>>(o_loss);

    // decoder (fp16x3) + heads (sem1/sem2/col1 fp16x2, col2 fp16x3)
    gemm_f16x<128, 1, false, 1, 3><<<dim3(1, 512), 256, GM_SMEM_128>>>(
        p_zqh, p_zql, p_whi + OFF_DEC1, p_wlo + OFF_DEC1, nullptr,
        nullptr, p_s1h, p_s1l, BATCH, 128, 64);
    gemm_f16x<128, 1, false, 1, 3><<<dim3(2, 512), 256, GM_SMEM_128>>>(
        p_s1h, p_s1l, p_whi + OFF_DEC2, p_wlo + OFF_DEC2, nullptr,
        nullptr, p_s2h, p_s2l, BATCH, 256, 128);
    gemm_f16x<128, 1, false, 1, 3><<<dim3(4, 512), 256, GM_SMEM_128>>>(
        p_s2h, p_s2l, p_whi + OFF_DEC3, p_wlo + OFF_DEC3, nullptr,
        nullptr, p_s3h, p_s3l, BATCH, 512, 256);

    gemm_f16x<128, 0, true, 0, 2><<<dim3(12, 512), 256, GM_SMEM_128>>>(
        p_s3h, p_s3l, p_whi + OFF_SEM1, p_wlo + OFF_SEM1, sem_b1,
        p_hh, nullptr, nullptr, BATCH, 1536, 512);
    ln_pair<1536, 256><<<8192, 256>>>(p_hh, sem_lng, sem_lnb, p_hlh, p_hll);
    gemm_f16x<128, 0, true, 0, 2><<<dim3(6, 512), 256, GM_SMEM_128>>>(
        p_hlh, p_hll, p_whi + OFF_SEM2, p_wlo + OFF_SEM2, sem_b2,
        o_sem, nullptr, nullptr, BATCH, 768, 1536);

    gemm_f16x<128, 0, true, 0, 2><<<dim3(2, 512), 256, GM_SMEM_128>>>(
        p_s3h, p_s3l, p_whi + OFF_COL1, p_wlo + OFF_COL1, col_b1,
        p_chh, nullptr, nullptr, BATCH, 256, 512);
    ln_pair<256, 128><<<8192, 128>>>(p_chh, col_lng, col_lnb, p_chl, p_cll);
    gemm_f16x<64, 0, true, 0, 3><<<dim3(1, 512), 256, GM_SMEM_64>>>(
        p_chl, p_cll, p_whi + OFF_COL2, p_wlo + OFF_COL2, col_b2,
        o_col, nullptr, nullptr, BATCH, 64, 256);
}